// round 13
// baseline (speedup 1.0000x reference)
#include <cuda_runtime.h>
#include <cuda_bf16.h>
#include <cuda_fp16.h>
#include <math.h>
#include <stdint.h>

typedef unsigned long long ull;
typedef unsigned int u32;

// ---------------------------------------------------------------------------
// Problem constants
// ---------------------------------------------------------------------------
#define BEV 320
#define NCELL (BEV*BEV)
#define FEAT_H 128
#define FEAT_W 352
#define CCH 96
#define HID 64
#define NB 2

// conv-as-GEMM: fp16 2-term (w = wh + wl exact; x single fp16 duplicated)
// K = 192 = 3 slabs x 64. act rows: [b][y 322][slab 3][px 328][64 fp16]
#define NSLAB 3
#define W_IMG 12288        // weight slab image: 96 oc rows x 64 fp16 (128B rows)
#define ACT_SZ (328*128)   // one act slab row in smem
#define W_SZ (3*W_IMG)     // 3 kx images per round

#define SW128(o) ((o) ^ (((o) >> 3) & 0x70))

// ---------------------------------------------------------------------------
// Scratch
// ---------------------------------------------------------------------------
__device__ __align__(16) float g_tfeat[NB * FEAT_H * FEAT_W * CCH];
__device__ float g_K1[HID * HID];
__device__ float g_C1[3 * HID];
// prepacked weight images: [conv 2][ky*3+kx 9][slab 3][12288 B], swizzled
__device__ __align__(16) unsigned char g_wpack[2 * 9 * NSLAB * W_IMG];
// fp16 act rows (zero-init borders stay zero forever; interior rewritten each launch)
__device__ __align__(16) __half g_act0[(size_t)NB * 322 * NSLAB * 328 * 64];
__device__ __align__(16) __half g_act1[(size_t)NB * 322 * NSLAB * 328 * 64];

// ---------------------------------------------------------------------------
// Helpers
// ---------------------------------------------------------------------------
__device__ __forceinline__ u32 smem_u32(const void* p) {
    u32 a;
    asm("{ .reg .u64 t; cvta.to.shared.u64 t, %1; cvt.u32.u64 %0, t; }" : "=r"(a) : "l"(p));
    return a;
}
__device__ __forceinline__ void cpa16s(u32 dst, const void* src) {
    asm volatile("cp.async.ca.shared.global [%0], [%1], 16;\n" :: "r"(dst), "l"(src));
}
__device__ __forceinline__ void ldsm4(u32& r0, u32& r1, u32& r2, u32& r3, u32 a) {
    asm volatile("ldmatrix.sync.aligned.m8n8.x4.shared.b16 {%0,%1,%2,%3}, [%4];"
                 : "=r"(r0), "=r"(r1), "=r"(r2), "=r"(r3) : "r"(a));
}
__device__ __forceinline__ void ldsm2(u32& r0, u32& r1, u32 a) {
    asm volatile("ldmatrix.sync.aligned.m8n8.x2.shared.b16 {%0,%1}, [%2];"
                 : "=r"(r0), "=r"(r1) : "r"(a));
}
__device__ __forceinline__ void mma16816(float* c, const u32* a, const u32* bfr) {
    asm volatile(
        "mma.sync.aligned.m16n8k16.row.col.f32.f16.f16.f32 "
        "{%0,%1,%2,%3}, {%4,%5,%6,%7}, {%8,%9}, {%0,%1,%2,%3};"
        : "+f"(c[0]), "+f"(c[1]), "+f"(c[2]), "+f"(c[3])
        : "r"(a[0]), "r"(a[1]), "r"(a[2]), "r"(a[3]), "r"(bfr[0]), "r"(bfr[1]));
}
__device__ __forceinline__ u32 dup_h(float v) {
    u32 h = (u32)__half_as_ushort(__float2half_rn(v));
    return h | (h << 16);
}

// ---------------------------------------------------------------------------
// Kernel 1: transpose image_feats [B,C,H,W] -> g_tfeat [B,H,W,C]
// ---------------------------------------------------------------------------
__global__ void transpose_kernel(const float* __restrict__ in)
{
    __shared__ float s[32][33];
    int tx = threadIdx.x, ty = threadIdx.y;
    int x0 = blockIdx.x * 32;
    int c0 = blockIdx.y * 32;
    int z  = blockIdx.z;
    int b = z >> 7, y = z & 127;
#pragma unroll
    for (int r = 0; r < 4; ++r) {
        int c = c0 + ty + r * 8;
        s[ty + r * 8][tx] = in[(((size_t)b * CCH + c) * FEAT_H + y) * FEAT_W + x0 + tx];
    }
    __syncthreads();
#pragma unroll
    for (int r = 0; r < 4; ++r) {
        int xo = ty + r * 8;
        g_tfeat[(((size_t)b * FEAT_H + y) * FEAT_W + x0 + xo) * CCH + c0 + tx] = s[tx][xo];
    }
}

// ---------------------------------------------------------------------------
// Kernel 2: fold depth-MLP into score-MLP hidden layer.
// ---------------------------------------------------------------------------
__global__ void prep_kernel(const float* __restrict__ dw2, const float* __restrict__ sw1,
                            const float* __restrict__ db2, const float* __restrict__ he,
                            const float* __restrict__ sb1)
{
    int j = threadIdx.x;
    int r = blockIdx.x;
    if (r < HID) {
        float a = 0.f;
        for (int c = 0; c < CCH; ++c) a = fmaf(dw2[r * CCH + c], sw1[c * HID + j], a);
        g_K1[r * HID + j] = a;
    } else {
        int h = r - HID;
        float a = sb1[j];
        for (int c = 0; c < CCH; ++c) a = fmaf(db2[c] + he[h * CCH + c], sw1[c * HID + j], a);
        g_C1[h * HID + j] = a;
    }
}

// ---------------------------------------------------------------------------
// Kernel W: prepack weights: wh = fp16(w) at k=2ic, wl = fp16(w-wh) at k=2ic+1.
// ---------------------------------------------------------------------------
__global__ void prep_wpack_kernel(const float* __restrict__ w1,
                                  const float* __restrict__ w2)
{
    int blk = blockIdx.x;            // conv*27 + kk*3 + slab
    int conv = blk / 27;
    int r = blk % 27;
    int kk = r / 3;
    int slab = r % 3;
    int ky = kk / 3, kx = kk % 3;
    const float* W = conv ? w2 : w1;
    unsigned char* img = g_wpack + (size_t)blk * W_IMG;

    for (int i = threadIdx.x; i < 96 * 64; i += 256) {
        int oc = i >> 6, k64 = i & 63;
        int K = slab * 64 + k64;
        int ic = K >> 1, t = K & 1;
        float wv = W[(size_t)oc * 864 + ic * 9 + ky * 3 + kx];
        __half wh = __float2half_rn(wv);
        __half val = t ? __float2half_rn(wv - __half2float(wh)) : wh;
        u32 off = SW128((u32)(oc * 128 + k64 * 2));
        *(__half*)(img + off) = val;
    }
}

// ---------------------------------------------------------------------------
// Kernel 3: BEV lift — merged-height MLP with smem hv table + token broadcast
// (unchanged from R12 best).
// ---------------------------------------------------------------------------
__global__ void __launch_bounds__(256, 3)
lift_kernel(const float* __restrict__ l2i, const float* __restrict__ sw1,
            const float* __restrict__ dw1, const float* __restrict__ db1,
            const float* __restrict__ sw2, const float* __restrict__ sb2p)
{
    extern __shared__ float sm[];
    float2* s_sw1 = (float2*)sm;
    float2* s_K1  = s_sw1 + CCH * 32;
    float2* s_dwb = s_K1 + HID * 32;
    float*  s_C1  = (float*)(s_dwb + 64);
    float*  s_sw2 = s_C1 + 192;
    float4* s_tok = (float4*)(s_sw2 + 64);
    float4* s_hv  = s_tok + 8 * 96;
    u32*    s_act3 = (u32*)(s_hv + 8 * 64);

    int tid = threadIdx.x;
    int w = tid >> 5, lane = tid & 31;
    int j0 = 2 * lane;
    float4* s_tokw = s_tok + w * 96;
    float4* s_hvw  = s_hv + w * 64;

    for (int i = tid; i < CCH * 32; i += 256) s_sw1[i] = ((const float2*)sw1)[i];
    for (int i = tid; i < HID * 32; i += 256) s_K1[i] = ((const float2*)g_K1)[i];
    if (tid < 64) s_dwb[tid] = make_float2(dw1[tid], db1[tid]);
    if (tid < 192) s_C1[tid] = g_C1[tid];
    if (tid < 64) s_sw2[tid] = sw2[tid];
    __syncthreads();
    float sb2 = *sb2p;

    const int NTILES = NB * NCELL / 32;
    for (int tile = blockIdx.x; tile < NTILES; tile += gridDim.x) {
        int N0 = tile * 32;
        int b = (N0 >= NCELL) ? 1 : 0;
        int n0 = N0 - b * NCELL;
        int y = n0 / BEV;
        int x0 = n0 - y * BEV;

        const float* M = l2i + b * 16;
        float M00 = M[0], M01 = M[1], M02 = M[2],  M03 = M[3];
        float M10 = M[4], M11 = M[5], M12 = M[6],  M13 = M[7];
        float M20 = M[8], M21 = M[9], M22 = M[10], M23 = M[11];

        float py = ((float)y + 0.5f) / 320.0f * 102.4f - 51.2f;

        for (int cc = 0; cc < 4; ++cc) {
            int cj = w + cc * 8;
            int x = x0 + cj;
            float px = ((float)x + 0.5f) / 320.0f * 102.4f - 51.2f;
            float b0 = M00 * px + M01 * py + M03;
            float b1 = M10 * px + M11 * py + M13;
            float b2 = M20 * px + M21 * py + M23;

            float sv[3][3];
            float dd[3];
            bool  val[3];
            float lg[3];

#pragma unroll
            for (int h = 0; h < 3; ++h) {
                float fh = (float)h;
                float p0 = b0 + fh * M02;
                float p1 = b1 + fh * M12;
                float dep = b2 + fh * M22;
                float dn = fmaxf(dep, 1e-5f);
                float u = p0 / dn, v = p1 / dn;
                float gx = u / 351.0f * 2.0f - 1.0f;
                float gy = v / 127.0f * 2.0f - 1.0f;
                bool valid = (dep > 1e-3f) && (fabsf(gx) <= 1.0f) && (fabsf(gy) <= 1.0f);
                val[h] = valid;
                sv[0][h] = 0.f; sv[1][h] = 0.f; sv[2][h] = 0.f;
                dd[h] = 0.f;

                if (valid) {
                    float xs = (gx + 1.0f) * 0.5f * 351.0f;
                    float ys = (gy + 1.0f) * 0.5f * 127.0f;
                    float xf = floorf(xs), yf = floorf(ys);
                    float wx = xs - xf, wy = ys - yf;
                    int ix = (int)xf, iy = (int)yf;
                    int ix1 = ix + 1, iy1 = iy + 1;
                    float w00 = (1.f - wx) * (1.f - wy);
                    float w10 = wx * (1.f - wy);
                    float w01 = (1.f - wx) * wy;
                    float w11 = wx * wy;
                    if (ix1 > 351) { ix1 = 351; w10 = 0.f; w11 = 0.f; }
                    if (iy1 > 127) { iy1 = 127; w01 = 0.f; w11 = 0.f; }

                    int rowA = (b * FEAT_H + iy) * FEAT_W;
                    int rowB = (b * FEAT_H + iy1) * FEAT_W;
                    int o00 = (rowA + ix) * CCH + lane;
                    int o10 = (rowA + ix1) * CCH + lane;
                    int o01 = (rowB + ix) * CCH + lane;
                    int o11 = (rowB + ix1) * CCH + lane;
#pragma unroll
                    for (int k = 0; k < 3; ++k) {
                        float A  = g_tfeat[o00 + 32 * k];
                        float Bv = g_tfeat[o10 + 32 * k];
                        float Cv = g_tfeat[o01 + 32 * k];
                        float Dv = g_tfeat[o11 + 32 * k];
                        sv[k][h] = fmaf(w00, A, fmaf(w10, Bv, fmaf(w01, Cv, w11 * Dv)));
                    }
                    dd[h] = log1pf(fmaxf(dep, 1e-3f));
                }
            }

            bool anym = val[0] | val[1] | val[2];
            lg[0] = -INFINITY; lg[1] = -INFINITY; lg[2] = -INFINITY;

            if (anym) {
#pragma unroll
                for (int g = 0; g < 3; ++g)
                    s_tokw[g * 32 + lane] = make_float4(sv[g][0], sv[g][1], sv[g][2], 0.f);
#pragma unroll
                for (int kk2 = 0; kk2 < 2; ++kk2) {
                    int k = lane + 32 * kk2;
                    float2 db = s_dwb[k];
                    float hv0 = fmaxf(fmaf(dd[0], db.x, db.y), 0.f);
                    float hv1 = fmaxf(fmaf(dd[1], db.x, db.y), 0.f);
                    float hv2 = fmaxf(fmaf(dd[2], db.x, db.y), 0.f);
                    s_hvw[k] = make_float4(hv0, hv1, hv2, 0.f);
                }
                __syncwarp();

                float a00 = s_C1[j0],       a01 = s_C1[j0 + 1];
                float a10 = s_C1[64 + j0],  a11 = s_C1[64 + j0 + 1];
                float a20 = s_C1[128 + j0], a21 = s_C1[128 + j0 + 1];

#pragma unroll 8
                for (int k = 0; k < HID; ++k) {
                    float4 hv = s_hvw[k];
                    float2 kk = s_K1[k * 32 + lane];
                    a00 = fmaf(hv.x, kk.x, a00); a01 = fmaf(hv.x, kk.y, a01);
                    a10 = fmaf(hv.y, kk.x, a10); a11 = fmaf(hv.y, kk.y, a11);
                    a20 = fmaf(hv.z, kk.x, a20); a21 = fmaf(hv.z, kk.y, a21);
                }

#pragma unroll 8
                for (int c = 0; c < CCH; ++c) {
                    float4 t = s_tokw[c];
                    float2 ww = s_sw1[c * 32 + lane];
                    a00 = fmaf(t.x, ww.x, a00); a01 = fmaf(t.x, ww.y, a01);
                    a10 = fmaf(t.y, ww.x, a10); a11 = fmaf(t.y, ww.y, a11);
                    a20 = fmaf(t.z, ww.x, a20); a21 = fmaf(t.z, ww.y, a21);
                }

                float swa = s_sw2[j0], swb = s_sw2[j0 + 1];
                float p0 = fmaxf(a00, 0.f) * swa + fmaxf(a01, 0.f) * swb;
                float p1 = fmaxf(a10, 0.f) * swa + fmaxf(a11, 0.f) * swb;
                float p2 = fmaxf(a20, 0.f) * swa + fmaxf(a21, 0.f) * swb;
#pragma unroll
                for (int off = 16; off > 0; off >>= 1) {
                    p0 += __shfl_xor_sync(0xffffffffu, p0, off);
                    p1 += __shfl_xor_sync(0xffffffffu, p1, off);
                    p2 += __shfl_xor_sync(0xffffffffu, p2, off);
                }
                if (val[0]) lg[0] = p0 + sb2;
                if (val[1]) lg[1] = p1 + sb2;
                if (val[2]) lg[2] = p2 + sb2;
                __syncwarp();
            }

            float m = fmaxf(fmaxf(lg[0], lg[1]), lg[2]);
            float e0 = 0.f, e1 = 0.f, e2 = 0.f;
            if (m > -1e30f) {
                e0 = expf(lg[0] - m);
                e1 = expf(lg[1] - m);
                e2 = expf(lg[2] - m);
                float inv = 1.0f / (e0 + e1 + e2);
                e0 *= inv; e1 *= inv; e2 *= inv;
            }
#pragma unroll
            for (int g = 0; g < 3; ++g) {
                float f = sv[g][0] * e0 + sv[g][1] * e1 + sv[g][2] * e2;
                s_act3[g * 1024 + cj * 32 + lane] = dup_h(f);
            }
        }
        __syncthreads();
        {
            size_t rowb = ((size_t)b * 322 + y + 1) * 3;
            const uint4* src = (const uint4*)s_act3;
            for (int i = tid; i < 768; i += 256) {
                int slab = i >> 8;
                int rem = i & 255;
                int p = rem >> 3, ch = rem & 7;
                uint4 v = src[slab * 256 + p * 8 + ch];
                *(uint4*)((char*)g_act0 + ((rowb + slab) * 328 + x0 + p + 1) * 128 + ch * 16) = v;
            }
        }
        __syncthreads();
    }
}

// ---------------------------------------------------------------------------
// Kernel C<PHASE>: mma.sync fp16 2-term conv — 512 threads, oc-split warps.
// Warp = 48 oc (3 m16 tiles, wid>>3) x 40 px ((wid&7)*40). acc 60 regs.
// 16 warps = 4 warps/SMSP hides ldsm/staging latency at same mma floor.
// ---------------------------------------------------------------------------
template <int PHASE>
__global__ void __launch_bounds__(512, 1)
mma_conv_kernel(const float* __restrict__ gg, const float* __restrict__ bb_,
                const float* __restrict__ mm, const float* __restrict__ vv,
                float* __restrict__ outp)
{
    extern __shared__ __align__(128) char smc[];
    u32 base = smem_u32(smc);
    u32 actb2[2] = { base, base + ACT_SZ };
    u32 wb2[2]   = { base + 2 * ACT_SZ, base + 2 * ACT_SZ + W_SZ };

    const __half* srcAct = PHASE ? g_act1 : g_act0;

    int tid = threadIdx.x, wid = tid >> 5, lane = tid & 31;
    int rowid = blockIdx.x;
    int b = rowid / 320, y = rowid % 320;
    int och = wid >> 3;               // 0/1: oc half
    int wpx = (wid & 7) * 40;
    int l7 = lane & 7, g = lane >> 3;

    float acc[3][5][4];
#pragma unroll
    for (int mi = 0; mi < 3; ++mi)
#pragma unroll
        for (int nt = 0; nt < 5; ++nt)
#pragma unroll
            for (int c = 0; c < 4; ++c) acc[mi][nt][c] = 0.f;

    auto stage = [&](int r, int bufi) {
        int ky = r / 3, slab = r % 3;
        const char* asrc = (const char*)srcAct +
            (((size_t)b * 322 + y + ky) * 3 + slab) * 328 * 128;
        for (int idx = tid; idx < 2624; idx += 512) {
            int px = idx >> 3, ch = idx & 7;
            cpa16s(actb2[bufi] + px * 128 + ((ch * 16) ^ ((px & 7) << 4)),
                   asrc + (size_t)px * 128 + ch * 16);
        }
        const unsigned char* wsrc = g_wpack +
            (size_t)((PHASE * 9 + ky * 3) * 3 + slab) * W_IMG;
        for (int idx = tid; idx < 2304; idx += 512) {
            int c = idx / 768, j = idx - c * 768;
            cpa16s(wb2[bufi] + c * W_IMG + j * 16,
                   wsrc + (size_t)c * 3 * W_IMG + j * 16);
        }
        asm volatile("cp.async.commit_group;\n");
    };

    stage(0, 0);

    for (int r = 0; r < 9; ++r) {
        int bufi = r & 1;
        if (r + 1 < 9) {
            stage(r + 1, bufi ^ 1);
            asm volatile("cp.async.wait_group 1;\n");
        } else {
            asm volatile("cp.async.wait_group 0;\n");
        }
        __syncthreads();

        u32 actbuf = actb2[bufi];
#pragma unroll
        for (int kx = 0; kx < 3; ++kx) {
            u32 wimg = wb2[bufi] + kx * W_IMG;
#pragma unroll
            for (int kk = 0; kk < 4; ++kk) {
                int kc2 = 2 * kk;
                u32 af[3][4];
                {
                    int arow_off = ((g & 1) << 3) + l7;
                    int achunk = kc2 + (g >> 1);
                    u32 axor = (u32)(achunk * 16) ^ ((u32)l7 << 4);
#pragma unroll
                    for (int mi = 0; mi < 3; ++mi) {
                        int mt = och * 3 + mi;
                        u32 a = wimg + (mt * 16 + arow_off) * 128 + axor;
                        ldsm4(af[mi][0], af[mi][1], af[mi][2], af[mi][3], a);
                    }
                }
                u32 bf[5][2];
                {
                    int px0 = wpx + kx + ((g >> 1) << 3) + l7;
                    int chunk = kc2 + (g & 1);
                    u32 a0 = actbuf + px0 * 128 + (((u32)(chunk * 16)) ^ (((u32)px0 & 7) << 4));
                    ldsm4(bf[0][0], bf[0][1], bf[1][0], bf[1][1], a0);
                    int px1 = px0 + 16;
                    u32 a1 = actbuf + px1 * 128 + (((u32)(chunk * 16)) ^ (((u32)px1 & 7) << 4));
                    ldsm4(bf[2][0], bf[2][1], bf[3][0], bf[3][1], a1);
                    int px2 = wpx + kx + 32 + l7;
                    int ch2 = kc2 + (g & 1);
                    u32 a2 = actbuf + px2 * 128 + (((u32)(ch2 * 16)) ^ (((u32)px2 & 7) << 4));
                    ldsm2(bf[4][0], bf[4][1], a2);
                }
#pragma unroll
                for (int mi = 0; mi < 3; ++mi)
#pragma unroll
                    for (int nt = 0; nt < 5; ++nt)
                        mma16816(acc[mi][nt], af[mi], bf[nt]);
            }
        }
        __syncthreads();
    }

    // ---- epilogue: BN + ReLU ----
    int lrow = lane >> 2;
    int lcol = (lane & 3) * 2;

    if (PHASE == 0) {
        u32* s_ep = (u32*)smc;
#pragma unroll
        for (int mi = 0; mi < 3; ++mi) {
            int mt = och * 3 + mi;
            int oc0 = mt * 16 + lrow;
            int oc1 = oc0 + 8;
            float a0 = gg[oc0] * rsqrtf(vv[oc0] + 1e-3f);
            float e0 = bb_[oc0] - mm[oc0] * a0;
            float a1 = gg[oc1] * rsqrtf(vv[oc1] + 1e-3f);
            float e1 = bb_[oc1] - mm[oc1] * a1;
            int s0 = (oc0 >> 5) * 10240 + (oc0 & 31);
            int s1 = (oc1 >> 5) * 10240 + (oc1 & 31);
#pragma unroll
            for (int nt = 0; nt < 5; ++nt) {
                int px = wpx + nt * 8 + lcol;
                s_ep[s0 + px * 32]       = dup_h(fmaxf(fmaf(acc[mi][nt][0], a0, e0), 0.f));
                s_ep[s0 + (px + 1) * 32] = dup_h(fmaxf(fmaf(acc[mi][nt][1], a0, e0), 0.f));
                s_ep[s1 + px * 32]       = dup_h(fmaxf(fmaf(acc[mi][nt][2], a1, e1), 0.f));
                s_ep[s1 + (px + 1) * 32] = dup_h(fmaxf(fmaf(acc[mi][nt][3], a1, e1), 0.f));
            }
        }
        __syncthreads();
        const uint4* src = (const uint4*)s_ep;
        size_t rowb = ((size_t)b * 322 + y + 1) * 3;
        for (int idx = tid; idx < 7680; idx += 512) {
            int slab = idx / 2560;
            int rem = idx - slab * 2560;
            int p = rem >> 3, ch = rem & 7;
            uint4 v = src[slab * 2560 + p * 8 + ch];
            *(uint4*)((char*)g_act1 + ((rowb + slab) * 328 + p + 1) * 128 + ch * 16) = v;
        }
    } else {
#pragma unroll
        for (int mi = 0; mi < 3; ++mi) {
            int mt = och * 3 + mi;
            int oc0 = mt * 16 + lrow;
            int oc1 = oc0 + 8;
            float a0 = gg[oc0] * rsqrtf(vv[oc0] + 1e-3f);
            float e0 = bb_[oc0] - mm[oc0] * a0;
            float a1 = gg[oc1] * rsqrtf(vv[oc1] + 1e-3f);
            float e1 = bb_[oc1] - mm[oc1] * a1;
#pragma unroll
            for (int nt = 0; nt < 5; ++nt) {
                int px = wpx + nt * 8 + lcol;
                float v00 = fmaxf(fmaf(acc[mi][nt][0], a0, e0), 0.f);
                float v01 = fmaxf(fmaf(acc[mi][nt][1], a0, e0), 0.f);
                float v10 = fmaxf(fmaf(acc[mi][nt][2], a1, e1), 0.f);
                float v11 = fmaxf(fmaf(acc[mi][nt][3], a1, e1), 0.f);
                *reinterpret_cast<float2*>(
                    &outp[((size_t)(b * CCH + oc0) * BEV + y) * BEV + px]) =
                    make_float2(v00, v01);
                *reinterpret_cast<float2*>(
                    &outp[((size_t)(b * CCH + oc1) * BEV + y) * BEV + px]) =
                    make_float2(v10, v11);
            }
        }
    }
}

// ---------------------------------------------------------------------------
// Launch
// ---------------------------------------------------------------------------
extern "C" void kernel_launch(void* const* d_in, const int* in_sizes, int n_in,
                              void* d_out, int out_size)
{
    const float* feats = (const float*)d_in[0];
    const float* l2i   = (const float*)d_in[1];
    const float* he    = (const float*)d_in[2];
    const float* dw1   = (const float*)d_in[3];
    const float* db1   = (const float*)d_in[4];
    const float* dw2   = (const float*)d_in[5];
    const float* db2   = (const float*)d_in[6];
    const float* sw1   = (const float*)d_in[7];
    const float* sb1   = (const float*)d_in[8];
    const float* sw2   = (const float*)d_in[9];
    const float* sb2   = (const float*)d_in[10];
    const float* c1w   = (const float*)d_in[11];
    const float* b1g   = (const float*)d_in[12];
    const float* b1b   = (const float*)d_in[13];
    const float* b1m   = (const float*)d_in[14];
    const float* b1v   = (const float*)d_in[15];
    const float* c2w   = (const float*)d_in[16];
    const float* b2g   = (const float*)d_in[17];
    const float* b2b   = (const float*)d_in[18];
    const float* b2m   = (const float*)d_in[19];
    const float* b2v   = (const float*)d_in[20];
    float* out = (float*)d_out;

    transpose_kernel<<<dim3(11, 3, NB * FEAT_H), dim3(32, 8)>>>(feats);
    prep_kernel<<<HID + 3, HID>>>(dw2, sw1, db2, he, sb1);
    prep_wpack_kernel<<<54, 256>>>(c1w, c2w);

    size_t lsm = (size_t)(CCH * 32 + HID * 32 + 64) * 8 + (192 + 64) * 4 +
                 (size_t)8 * 96 * 16 + (size_t)8 * 64 * 16 + 3 * 32 * 32 * 4;
    cudaFuncSetAttribute(lift_kernel, cudaFuncAttributeMaxDynamicSharedMemorySize, (int)lsm);
    lift_kernel<<<444, 256, lsm>>>(l2i, sw1, dw1, db1, sw2, sb2);

    size_t csm = 2 * ACT_SZ + 2 * W_SZ;   // 157,696 B
    cudaFuncSetAttribute(mma_conv_kernel<0>, cudaFuncAttributeMaxDynamicSharedMemorySize, (int)csm);
    cudaFuncSetAttribute(mma_conv_kernel<1>, cudaFuncAttributeMaxDynamicSharedMemorySize, (int)csm);

    mma_conv_kernel<0><<<NB * BEV, 512, csm>>>(b1g, b1b, b1m, b1v, out);
    mma_conv_kernel<1><<<NB * BEV, 512, csm>>>(b2g, b2b, b2m, b2v, out);
}

// round 15
// speedup vs baseline: 1.1023x; 1.1023x over previous
#include <cuda_runtime.h>
#include <cuda_bf16.h>
#include <cuda_fp16.h>
#include <math.h>
#include <stdint.h>

typedef unsigned long long ull;
typedef unsigned int u32;

// ---------------------------------------------------------------------------
// Problem constants
// ---------------------------------------------------------------------------
#define BEV 320
#define NCELL (BEV*BEV)
#define FEAT_H 128
#define FEAT_W 352
#define CCH 96
#define HID 64
#define NB 2

// conv-as-GEMM: fp16 2-term (w = wh + wl exact; x single fp16 duplicated)
#define NSLAB 3
#define W_IMG 12288
#define ACT_SZ (328*128)
#define W_SZ (3*W_IMG)

#define SW128(o) ((o) ^ (((o) >> 3) & 0x70))

// ---------------------------------------------------------------------------
// Scratch
// ---------------------------------------------------------------------------
__device__ __align__(16) float g_tfeat[NB * FEAT_H * FEAT_W * CCH];
__device__ float g_K1[HID * HID];
__device__ float g_C1[3 * HID];
// piecewise-linear depth-MLP tables
__device__ float g_thr[HID];               // sorted relu knots
__device__ __align__(16) float g_segA[65 * HID];
__device__ __align__(16) float g_segB[65 * HID];
// prepacked weight images
__device__ __align__(16) unsigned char g_wpack[2 * 9 * NSLAB * W_IMG];
// fp16 act rows
__device__ __align__(16) __half g_act0[(size_t)NB * 322 * NSLAB * 328 * 64];
__device__ __align__(16) __half g_act1[(size_t)NB * 322 * NSLAB * 328 * 64];

// ---------------------------------------------------------------------------
// Helpers
// ---------------------------------------------------------------------------
__device__ __forceinline__ u32 smem_u32(const void* p) {
    u32 a;
    asm("{ .reg .u64 t; cvta.to.shared.u64 t, %1; cvt.u32.u64 %0, t; }" : "=r"(a) : "l"(p));
    return a;
}
__device__ __forceinline__ void cpa16s(u32 dst, const void* src) {
    asm volatile("cp.async.ca.shared.global [%0], [%1], 16;\n" :: "r"(dst), "l"(src));
}
__device__ __forceinline__ void ldsm4(u32& r0, u32& r1, u32& r2, u32& r3, u32 a) {
    asm volatile("ldmatrix.sync.aligned.m8n8.x4.shared.b16 {%0,%1,%2,%3}, [%4];"
                 : "=r"(r0), "=r"(r1), "=r"(r2), "=r"(r3) : "r"(a));
}
__device__ __forceinline__ void ldsm2(u32& r0, u32& r1, u32 a) {
    asm volatile("ldmatrix.sync.aligned.m8n8.x2.shared.b16 {%0,%1}, [%2];"
                 : "=r"(r0), "=r"(r1) : "r"(a));
}
__device__ __forceinline__ void mma16816(float* c, const u32* a, const u32* bfr) {
    asm volatile(
        "mma.sync.aligned.m16n8k16.row.col.f32.f16.f16.f32 "
        "{%0,%1,%2,%3}, {%4,%5,%6,%7}, {%8,%9}, {%0,%1,%2,%3};"
        : "+f"(c[0]), "+f"(c[1]), "+f"(c[2]), "+f"(c[3])
        : "r"(a[0]), "r"(a[1]), "r"(a[2]), "r"(a[3]), "r"(bfr[0]), "r"(bfr[1]));
}
__device__ __forceinline__ u32 dup_h(float v) {
    u32 h = (u32)__half_as_ushort(__float2half_rn(v));
    return h | (h << 16);
}

// ---------------------------------------------------------------------------
// Kernel 1: transpose image_feats [B,C,H,W] -> g_tfeat [B,H,W,C]
// ---------------------------------------------------------------------------
__global__ void transpose_kernel(const float* __restrict__ in)
{
    __shared__ float s[32][33];
    int tx = threadIdx.x, ty = threadIdx.y;
    int x0 = blockIdx.x * 32;
    int c0 = blockIdx.y * 32;
    int z  = blockIdx.z;
    int b = z >> 7, y = z & 127;
#pragma unroll
    for (int r = 0; r < 4; ++r) {
        int c = c0 + ty + r * 8;
        s[ty + r * 8][tx] = in[(((size_t)b * CCH + c) * FEAT_H + y) * FEAT_W + x0 + tx];
    }
    __syncthreads();
#pragma unroll
    for (int r = 0; r < 4; ++r) {
        int xo = ty + r * 8;
        g_tfeat[(((size_t)b * FEAT_H + y) * FEAT_W + x0 + xo) * CCH + c0 + tx] = s[tx][xo];
    }
}

// ---------------------------------------------------------------------------
// Kernel 2: fold depth-MLP into score-MLP hidden layer.
// ---------------------------------------------------------------------------
__global__ void prep_kernel(const float* __restrict__ dw2, const float* __restrict__ sw1,
                            const float* __restrict__ db2, const float* __restrict__ he,
                            const float* __restrict__ sb1)
{
    int j = threadIdx.x;
    int r = blockIdx.x;
    if (r < HID) {
        float a = 0.f;
        for (int c = 0; c < CCH; ++c) a = fmaf(dw2[r * CCH + c], sw1[c * HID + j], a);
        g_K1[r * HID + j] = a;
    } else {
        int h = r - HID;
        float a = sb1[j];
        for (int c = 0; c < CCH; ++c) a = fmaf(db2[c] + he[h * CCH + c], sw1[c * HID + j], a);
        g_C1[h * HID + j] = a;
    }
}

// ---------------------------------------------------------------------------
// Kernel 2b: sort relu knots of the depth MLP (rank sort, 1 block x 64).
// ---------------------------------------------------------------------------
__global__ void prep_seg1_kernel(const float* __restrict__ dw1,
                                 const float* __restrict__ db1)
{
    __shared__ float tau[HID];
    int k = threadIdx.x;
    float dw = dw1[k];
    tau[k] = (dw != 0.f) ? (-db1[k] / dw) : 1e30f;
    __syncthreads();
    float mine = tau[k];
    int rank = 0;
    for (int j = 0; j < HID; ++j) {
        float o = tau[j];
        if (o < mine || (o == mine && j < k)) ++rank;
    }
    g_thr[rank] = mine;
}

// ---------------------------------------------------------------------------
// Kernel 2c: per-segment slope/intercept sums (grid 65, block 64).
//   f_j(d) = A[s][j]*d + B[s][j]  for d in segment s.
// ---------------------------------------------------------------------------
__global__ void prep_seg2_kernel(const float* __restrict__ dw1,
                                 const float* __restrict__ db1)
{
    int s = blockIdx.x;        // 0..64
    int j = threadIdx.x;
    float lo = (s == 0) ? g_thr[0] - 1.0f : g_thr[s - 1];
    float hi = (s == 64) ? g_thr[63] + 1.0f : g_thr[s];
    float mid = 0.5f * lo + 0.5f * hi;
    float A = 0.f, B = 0.f;
    for (int k = 0; k < HID; ++k) {
        float dw = dw1[k], db = db1[k];
        if (fmaf(mid, dw, db) > 0.f) {
            float k1 = g_K1[k * HID + j];
            A = fmaf(dw, k1, A);
            B = fmaf(db, k1, B);
        }
    }
    g_segA[s * HID + j] = A;
    g_segB[s * HID + j] = B;
}

// ---------------------------------------------------------------------------
// Kernel W: prepack weights: wh = fp16(w) at k=2ic, wl = fp16(w-wh) at k=2ic+1.
// ---------------------------------------------------------------------------
__global__ void prep_wpack_kernel(const float* __restrict__ w1,
                                  const float* __restrict__ w2)
{
    int blk = blockIdx.x;
    int conv = blk / 27;
    int r = blk % 27;
    int kk = r / 3;
    int slab = r % 3;
    int ky = kk / 3, kx = kk % 3;
    const float* W = conv ? w2 : w1;
    unsigned char* img = g_wpack + (size_t)blk * W_IMG;

    for (int i = threadIdx.x; i < 96 * 64; i += 256) {
        int oc = i >> 6, k64 = i & 63;
        int K = slab * 64 + k64;
        int ic = K >> 1, t = K & 1;
        float wv = W[(size_t)oc * 864 + ic * 9 + ky * 3 + kx];
        __half wh = __float2half_rn(wv);
        __half val = t ? __float2half_rn(wv - __half2float(wh)) : wh;
        u32 off = SW128((u32)(oc * 128 + k64 * 2));
        *(__half*)(img + off) = val;
    }
}

// ---------------------------------------------------------------------------
// Kernel 3: BEV lift — token-broadcast channel loop + piecewise-linear depth
// MLP. FIX vs R14: binary search offset starts at 64 so segment 64 reachable.
// ---------------------------------------------------------------------------
__global__ void __launch_bounds__(256, 3)
lift_kernel(const float* __restrict__ l2i, const float* __restrict__ sw1,
            const float* __restrict__ sw2, const float* __restrict__ sb2p)
{
    extern __shared__ float sm[];
    float2* s_sw1 = (float2*)sm;              // 96*32 float2  (24576 B)
    float*  s_C1  = (float*)(s_sw1 + CCH * 32); // 192
    float*  s_sw2 = s_C1 + 192;               // 64
    float*  s_thr = s_sw2 + 64;               // 64
    float4* s_tok = (float4*)(s_thr + 64);    // 8 warps x 96 (12288 B)
    u32*    s_act3 = (u32*)(s_tok + 8 * 96);  // [3][32][32]  (12288 B)

    int tid = threadIdx.x;
    int w = tid >> 5, lane = tid & 31;
    int j0 = 2 * lane;
    float4* s_tokw = s_tok + w * 96;

    for (int i = tid; i < CCH * 32; i += 256) s_sw1[i] = ((const float2*)sw1)[i];
    if (tid < 192) s_C1[tid] = g_C1[tid];
    if (tid < 64) s_sw2[tid] = sw2[tid];
    if (tid < 64) s_thr[tid] = g_thr[tid];
    __syncthreads();
    float sb2 = *sb2p;

    const int NTILES = NB * NCELL / 32;
    for (int tile = blockIdx.x; tile < NTILES; tile += gridDim.x) {
        int N0 = tile * 32;
        int b = (N0 >= NCELL) ? 1 : 0;
        int n0 = N0 - b * NCELL;
        int y = n0 / BEV;
        int x0 = n0 - y * BEV;

        const float* M = l2i + b * 16;
        float M00 = M[0], M01 = M[1], M02 = M[2],  M03 = M[3];
        float M10 = M[4], M11 = M[5], M12 = M[6],  M13 = M[7];
        float M20 = M[8], M21 = M[9], M22 = M[10], M23 = M[11];

        float py = ((float)y + 0.5f) / 320.0f * 102.4f - 51.2f;

        for (int cc = 0; cc < 4; ++cc) {
            int cj = w + cc * 8;
            int x = x0 + cj;
            float px = ((float)x + 0.5f) / 320.0f * 102.4f - 51.2f;
            float b0 = M00 * px + M01 * py + M03;
            float b1 = M10 * px + M11 * py + M13;
            float b2 = M20 * px + M21 * py + M23;

            float sv[3][3];
            float dd[3];
            bool  val[3];
            float lg[3];

#pragma unroll
            for (int h = 0; h < 3; ++h) {
                float fh = (float)h;
                float p0 = b0 + fh * M02;
                float p1 = b1 + fh * M12;
                float dep = b2 + fh * M22;
                float dn = fmaxf(dep, 1e-5f);
                float u = p0 / dn, v = p1 / dn;
                float gx = u / 351.0f * 2.0f - 1.0f;
                float gy = v / 127.0f * 2.0f - 1.0f;
                bool valid = (dep > 1e-3f) && (fabsf(gx) <= 1.0f) && (fabsf(gy) <= 1.0f);
                val[h] = valid;
                sv[0][h] = 0.f; sv[1][h] = 0.f; sv[2][h] = 0.f;
                dd[h] = 0.f;

                if (valid) {
                    float xs = (gx + 1.0f) * 0.5f * 351.0f;
                    float ys = (gy + 1.0f) * 0.5f * 127.0f;
                    float xf = floorf(xs), yf = floorf(ys);
                    float wx = xs - xf, wy = ys - yf;
                    int ix = (int)xf, iy = (int)yf;
                    int ix1 = ix + 1, iy1 = iy + 1;
                    float w00 = (1.f - wx) * (1.f - wy);
                    float w10 = wx * (1.f - wy);
                    float w01 = (1.f - wx) * wy;
                    float w11 = wx * wy;
                    if (ix1 > 351) { ix1 = 351; w10 = 0.f; w11 = 0.f; }
                    if (iy1 > 127) { iy1 = 127; w01 = 0.f; w11 = 0.f; }

                    int rowA = (b * FEAT_H + iy) * FEAT_W;
                    int rowB = (b * FEAT_H + iy1) * FEAT_W;
                    int o00 = (rowA + ix) * CCH + lane;
                    int o10 = (rowA + ix1) * CCH + lane;
                    int o01 = (rowB + ix) * CCH + lane;
                    int o11 = (rowB + ix1) * CCH + lane;
#pragma unroll
                    for (int k = 0; k < 3; ++k) {
                        float A  = g_tfeat[o00 + 32 * k];
                        float Bv = g_tfeat[o10 + 32 * k];
                        float Cv = g_tfeat[o01 + 32 * k];
                        float Dv = g_tfeat[o11 + 32 * k];
                        sv[k][h] = fmaf(w00, A, fmaf(w10, Bv, fmaf(w01, Cv, w11 * Dv)));
                    }
                    dd[h] = log1pf(fmaxf(dep, 1e-3f));
                }
            }

            bool anym = val[0] | val[1] | val[2];
            lg[0] = -INFINITY; lg[1] = -INFINITY; lg[2] = -INFINITY;

            if (anym) {   // warp-uniform
#pragma unroll
                for (int g = 0; g < 3; ++g)
                    s_tokw[g * 32 + lane] = make_float4(sv[g][0], sv[g][1], sv[g][2], 0.f);
                __syncwarp();

                // piecewise-linear depth MLP: segment = #(thr <= d), 0..64
                int seg[3];
#pragma unroll
                for (int h = 0; h < 3; ++h) {
                    float d = dd[h];
                    int s = 0;
#pragma unroll
                    for (int off = 64; off > 0; off >>= 1) {
                        int t = s + off;
                        if (t <= 64 && s_thr[t - 1] <= d) s = t;
                    }
                    seg[h] = s;
                }
                float2 A0 = ((const float2*)(g_segA + seg[0] * HID))[lane];
                float2 B0 = ((const float2*)(g_segB + seg[0] * HID))[lane];
                float2 A1 = ((const float2*)(g_segA + seg[1] * HID))[lane];
                float2 B1 = ((const float2*)(g_segB + seg[1] * HID))[lane];
                float2 A2 = ((const float2*)(g_segA + seg[2] * HID))[lane];
                float2 B2 = ((const float2*)(g_segB + seg[2] * HID))[lane];

                float a00 = s_C1[j0]       + fmaf(A0.x, dd[0], B0.x);
                float a01 = s_C1[j0 + 1]   + fmaf(A0.y, dd[0], B0.y);
                float a10 = s_C1[64 + j0]  + fmaf(A1.x, dd[1], B1.x);
                float a11 = s_C1[64 + j0 + 1] + fmaf(A1.y, dd[1], B1.y);
                float a20 = s_C1[128 + j0] + fmaf(A2.x, dd[2], B2.x);
                float a21 = s_C1[128 + j0 + 1] + fmaf(A2.y, dd[2], B2.y);

#pragma unroll 8
                for (int c = 0; c < CCH; ++c) {
                    float4 t = s_tokw[c];                 // uniform -> broadcast
                    float2 ww = s_sw1[c * 32 + lane];
                    a00 = fmaf(t.x, ww.x, a00); a01 = fmaf(t.x, ww.y, a01);
                    a10 = fmaf(t.y, ww.x, a10); a11 = fmaf(t.y, ww.y, a11);
                    a20 = fmaf(t.z, ww.x, a20); a21 = fmaf(t.z, ww.y, a21);
                }

                float swa = s_sw2[j0], swb = s_sw2[j0 + 1];
                float p0 = fmaxf(a00, 0.f) * swa + fmaxf(a01, 0.f) * swb;
                float p1 = fmaxf(a10, 0.f) * swa + fmaxf(a11, 0.f) * swb;
                float p2 = fmaxf(a20, 0.f) * swa + fmaxf(a21, 0.f) * swb;
#pragma unroll
                for (int off = 16; off > 0; off >>= 1) {
                    p0 += __shfl_xor_sync(0xffffffffu, p0, off);
                    p1 += __shfl_xor_sync(0xffffffffu, p1, off);
                    p2 += __shfl_xor_sync(0xffffffffu, p2, off);
                }
                if (val[0]) lg[0] = p0 + sb2;
                if (val[1]) lg[1] = p1 + sb2;
                if (val[2]) lg[2] = p2 + sb2;
                __syncwarp();
            }

            float m = fmaxf(fmaxf(lg[0], lg[1]), lg[2]);
            float e0 = 0.f, e1 = 0.f, e2 = 0.f;
            if (m > -1e30f) {
                e0 = expf(lg[0] - m);
                e1 = expf(lg[1] - m);
                e2 = expf(lg[2] - m);
                float inv = 1.0f / (e0 + e1 + e2);
                e0 *= inv; e1 *= inv; e2 *= inv;
            }
#pragma unroll
            for (int g = 0; g < 3; ++g) {
                float f = sv[g][0] * e0 + sv[g][1] * e1 + sv[g][2] * e2;
                s_act3[g * 1024 + cj * 32 + lane] = dup_h(f);
            }
        }
        __syncthreads();
        {
            size_t rowb = ((size_t)b * 322 + y + 1) * 3;
            const uint4* src = (const uint4*)s_act3;
            for (int i = tid; i < 768; i += 256) {
                int slab = i >> 8;
                int rem = i & 255;
                int p = rem >> 3, ch = rem & 7;
                uint4 v = src[slab * 256 + p * 8 + ch];
                *(uint4*)((char*)g_act0 + ((rowb + slab) * 328 + x0 + p + 1) * 128 + ch * 16) = v;
            }
        }
        __syncthreads();
    }
}

// ---------------------------------------------------------------------------
// Kernel C<PHASE>: mma.sync fp16 2-term conv — R12 best (256 thr, warp=96x40).
// ---------------------------------------------------------------------------
template <int PHASE>
__global__ void __launch_bounds__(256, 1)
mma_conv_kernel(const float* __restrict__ gg, const float* __restrict__ bb_,
                const float* __restrict__ mm, const float* __restrict__ vv,
                float* __restrict__ outp)
{
    extern __shared__ __align__(128) char smc[];
    u32 base = smem_u32(smc);
    u32 actb2[2] = { base, base + ACT_SZ };
    u32 wb2[2]   = { base + 2 * ACT_SZ, base + 2 * ACT_SZ + W_SZ };

    const __half* srcAct = PHASE ? g_act1 : g_act0;

    int tid = threadIdx.x, wid = tid >> 5, lane = tid & 31;
    int rowid = blockIdx.x;
    int b = rowid / 320, y = rowid % 320;
    int wpx = wid * 40;
    int l7 = lane & 7, g = lane >> 3;

    float acc[6][5][4];
#pragma unroll
    for (int mi = 0; mi < 6; ++mi)
#pragma unroll
        for (int nt = 0; nt < 5; ++nt)
#pragma unroll
            for (int c = 0; c < 4; ++c) acc[mi][nt][c] = 0.f;

    auto stage = [&](int r, int bufi) {
        int ky = r / 3, slab = r % 3;
        const char* asrc = (const char*)srcAct +
            (((size_t)b * 322 + y + ky) * 3 + slab) * 328 * 128;
        for (int idx = tid; idx < 2624; idx += 256) {
            int px = idx >> 3, ch = idx & 7;
            cpa16s(actb2[bufi] + px * 128 + ((ch * 16) ^ ((px & 7) << 4)),
                   asrc + (size_t)px * 128 + ch * 16);
        }
        const unsigned char* wsrc = g_wpack +
            (size_t)((PHASE * 9 + ky * 3) * 3 + slab) * W_IMG;
        for (int idx = tid; idx < 2304; idx += 256) {
            int c = idx / 768, j = idx - c * 768;
            cpa16s(wb2[bufi] + c * W_IMG + j * 16,
                   wsrc + (size_t)c * 3 * W_IMG + j * 16);
        }
        asm volatile("cp.async.commit_group;\n");
    };

    stage(0, 0);

    for (int r = 0; r < 9; ++r) {
        int bufi = r & 1;
        if (r + 1 < 9) {
            stage(r + 1, bufi ^ 1);
            asm volatile("cp.async.wait_group 1;\n");
        } else {
            asm volatile("cp.async.wait_group 0;\n");
        }
        __syncthreads();

        u32 actbuf = actb2[bufi];
#pragma unroll
        for (int kx = 0; kx < 3; ++kx) {
            u32 wimg = wb2[bufi] + kx * W_IMG;
#pragma unroll
            for (int kk = 0; kk < 4; ++kk) {
                int kc2 = 2 * kk;
                u32 af[6][4];
                {
                    int arow_off = ((g & 1) << 3) + l7;
                    int achunk = kc2 + (g >> 1);
                    u32 axor = (u32)(achunk * 16) ^ ((u32)l7 << 4);
#pragma unroll
                    for (int mi = 0; mi < 6; ++mi) {
                        u32 a = wimg + (mi * 16 + arow_off) * 128 + axor;
                        ldsm4(af[mi][0], af[mi][1], af[mi][2], af[mi][3], a);
                    }
                }
                u32 bf[5][2];
                {
                    int px0 = wpx + kx + ((g >> 1) << 3) + l7;
                    int chunk = kc2 + (g & 1);
                    u32 a0 = actbuf + px0 * 128 + (((u32)(chunk * 16)) ^ (((u32)px0 & 7) << 4));
                    ldsm4(bf[0][0], bf[0][1], bf[1][0], bf[1][1], a0);
                    int px1 = px0 + 16;
                    u32 a1 = actbuf + px1 * 128 + (((u32)(chunk * 16)) ^ (((u32)px1 & 7) << 4));
                    ldsm4(bf[2][0], bf[2][1], bf[3][0], bf[3][1], a1);
                    int px2 = wpx + kx + 32 + l7;
                    int ch2 = kc2 + (g & 1);
                    u32 a2 = actbuf + px2 * 128 + (((u32)(ch2 * 16)) ^ (((u32)px2 & 7) << 4));
                    ldsm2(bf[4][0], bf[4][1], a2);
                }
#pragma unroll
                for (int mi = 0; mi < 6; ++mi)
#pragma unroll
                    for (int nt = 0; nt < 5; ++nt)
                        mma16816(acc[mi][nt], af[mi], bf[nt]);
            }
        }
        __syncthreads();
    }

    // ---- epilogue: BN + ReLU ----
    int lrow = lane >> 2;
    int lcol = (lane & 3) * 2;

    if (PHASE == 0) {
        u32* s_ep = (u32*)smc;
#pragma unroll
        for (int mi = 0; mi < 6; ++mi) {
            int oc0 = mi * 16 + lrow;
            int oc1 = oc0 + 8;
            float a0 = gg[oc0] * rsqrtf(vv[oc0] + 1e-3f);
            float e0 = bb_[oc0] - mm[oc0] * a0;
            float a1 = gg[oc1] * rsqrtf(vv[oc1] + 1e-3f);
            float e1 = bb_[oc1] - mm[oc1] * a1;
            int s0 = (oc0 >> 5) * 10240 + (oc0 & 31);
            int s1 = (oc1 >> 5) * 10240 + (oc1 & 31);
#pragma unroll
            for (int nt = 0; nt < 5; ++nt) {
                int px = wpx + nt * 8 + lcol;
                s_ep[s0 + px * 32]       = dup_h(fmaxf(fmaf(acc[mi][nt][0], a0, e0), 0.f));
                s_ep[s0 + (px + 1) * 32] = dup_h(fmaxf(fmaf(acc[mi][nt][1], a0, e0), 0.f));
                s_ep[s1 + px * 32]       = dup_h(fmaxf(fmaf(acc[mi][nt][2], a1, e1), 0.f));
                s_ep[s1 + (px + 1) * 32] = dup_h(fmaxf(fmaf(acc[mi][nt][3], a1, e1), 0.f));
            }
        }
        __syncthreads();
        const uint4* src = (const uint4*)s_ep;
        size_t rowb = ((size_t)b * 322 + y + 1) * 3;
        for (int idx = tid; idx < 7680; idx += 256) {
            int slab = idx / 2560;
            int rem = idx - slab * 2560;
            int p = rem >> 3, ch = rem & 7;
            uint4 v = src[slab * 2560 + p * 8 + ch];
            *(uint4*)((char*)g_act1 + ((rowb + slab) * 328 + p + 1) * 128 + ch * 16) = v;
        }
    } else {
#pragma unroll
        for (int mi = 0; mi < 6; ++mi) {
            int oc0 = mi * 16 + lrow;
            int oc1 = oc0 + 8;
            float a0 = gg[oc0] * rsqrtf(vv[oc0] + 1e-3f);
            float e0 = bb_[oc0] - mm[oc0] * a0;
            float a1 = gg[oc1] * rsqrtf(vv[oc1] + 1e-3f);
            float e1 = bb_[oc1] - mm[oc1] * a1;
#pragma unroll
            for (int nt = 0; nt < 5; ++nt) {
                int px = wpx + nt * 8 + lcol;
                float v00 = fmaxf(fmaf(acc[mi][nt][0], a0, e0), 0.f);
                float v01 = fmaxf(fmaf(acc[mi][nt][1], a0, e0), 0.f);
                float v10 = fmaxf(fmaf(acc[mi][nt][2], a1, e1), 0.f);
                float v11 = fmaxf(fmaf(acc[mi][nt][3], a1, e1), 0.f);
                *reinterpret_cast<float2*>(
                    &outp[((size_t)(b * CCH + oc0) * BEV + y) * BEV + px]) =
                    make_float2(v00, v01);
                *reinterpret_cast<float2*>(
                    &outp[((size_t)(b * CCH + oc1) * BEV + y) * BEV + px]) =
                    make_float2(v10, v11);
            }
        }
    }
}

// ---------------------------------------------------------------------------
// Launch
// ---------------------------------------------------------------------------
extern "C" void kernel_launch(void* const* d_in, const int* in_sizes, int n_in,
                              void* d_out, int out_size)
{
    const float* feats = (const float*)d_in[0];
    const float* l2i   = (const float*)d_in[1];
    const float* he    = (const float*)d_in[2];
    const float* dw1   = (const float*)d_in[3];
    const float* db1   = (const float*)d_in[4];
    const float* dw2   = (const float*)d_in[5];
    const float* db2   = (const float*)d_in[6];
    const float* sw1   = (const float*)d_in[7];
    const float* sb1   = (const float*)d_in[8];
    const float* sw2   = (const float*)d_in[9];
    const float* sb2   = (const float*)d_in[10];
    const float* c1w   = (const float*)d_in[11];
    const float* b1g   = (const float*)d_in[12];
    const float* b1b   = (const float*)d_in[13];
    const float* b1m   = (const float*)d_in[14];
    const float* b1v   = (const float*)d_in[15];
    const float* c2w   = (const float*)d_in[16];
    const float* b2g   = (const float*)d_in[17];
    const float* b2b   = (const float*)d_in[18];
    const float* b2m   = (const float*)d_in[19];
    const float* b2v   = (const float*)d_in[20];
    float* out = (float*)d_out;

    transpose_kernel<<<dim3(11, 3, NB * FEAT_H), dim3(32, 8)>>>(feats);
    prep_kernel<<<HID + 3, HID>>>(dw2, sw1, db2, he, sb1);
    prep_seg1_kernel<<<1, HID>>>(dw1, db1);
    prep_seg2_kernel<<<65, HID>>>(dw1, db1);
    prep_wpack_kernel<<<54, 256>>>(c1w, c2w);

    // lift smem: sw1 + C1 + sw2 + thr + tok + act3
    size_t lsm = (size_t)(CCH * 32) * 8 + (192 + 64 + 64) * 4 +
                 (size_t)8 * 96 * 16 + 3 * 32 * 32 * 4;
    cudaFuncSetAttribute(lift_kernel, cudaFuncAttributeMaxDynamicSharedMemorySize, (int)lsm);
    lift_kernel<<<444, 256, lsm>>>(l2i, sw1, sw2, sb2);

    size_t csm = 2 * ACT_SZ + 2 * W_SZ;   // 157,696 B
    cudaFuncSetAttribute(mma_conv_kernel<0>, cudaFuncAttributeMaxDynamicSharedMemorySize, (int)csm);
    cudaFuncSetAttribute(mma_conv_kernel<1>, cudaFuncAttributeMaxDynamicSharedMemorySize, (int)csm);

    mma_conv_kernel<0><<<NB * BEV, 256, csm>>>(b1g, b1b, b1m, b1v, out);
    mma_conv_kernel<1><<<NB * BEV, 256, csm>>>(b2g, b2b, b2m, b2v, out);
}

// round 16
// speedup vs baseline: 1.3657x; 1.2389x over previous
#include <cuda_runtime.h>
#include <cuda_bf16.h>
#include <cuda_fp16.h>
#include <math.h>
#include <stdint.h>

typedef unsigned long long ull;
typedef unsigned int u32;

// ---------------------------------------------------------------------------
// Problem constants
// ---------------------------------------------------------------------------
#define BEV 320
#define NCELL (BEV*BEV)
#define FEAT_H 128
#define FEAT_W 352
#define CCH 96
#define HID 64
#define NB 2

// conv-as-GEMM: single-fp16 weights, K = 96 real padded to 128 (2 slabs x 64).
// act rows: [b][y 322][slab 2][px 328][64 fp16]; slab1 slots 32..63 = 0.
#define NSLAB 2
#define W_IMG 12288        // weight slab image: 96 oc rows x 64 fp16 (128B rows)
#define ACT_SZ (328*128)   // one act slab row in smem
#define W_SZ (3*W_IMG)     // 3 kx images per round

#define SW128(o) ((o) ^ (((o) >> 3) & 0x70))

// ---------------------------------------------------------------------------
// Scratch
// ---------------------------------------------------------------------------
__device__ __align__(16) float g_tfeat[NB * FEAT_H * FEAT_W * CCH];
__device__ float g_K1[HID * HID];
__device__ float g_C1[3 * HID];
// piecewise-linear depth-MLP tables
__device__ float g_thr[HID];
__device__ __align__(16) float g_segA[65 * HID];
__device__ __align__(16) float g_segB[65 * HID];
// prepacked weight images: [conv 2][ky*3+kx 9][slab 2][12288 B], swizzled
__device__ __align__(16) unsigned char g_wpack[2 * 9 * NSLAB * W_IMG];
// fp16 act rows
__device__ __align__(16) __half g_act0[(size_t)NB * 322 * NSLAB * 328 * 64];
__device__ __align__(16) __half g_act1[(size_t)NB * 322 * NSLAB * 328 * 64];

// ---------------------------------------------------------------------------
// Helpers
// ---------------------------------------------------------------------------
__device__ __forceinline__ u32 smem_u32(const void* p) {
    u32 a;
    asm("{ .reg .u64 t; cvta.to.shared.u64 t, %1; cvt.u32.u64 %0, t; }" : "=r"(a) : "l"(p));
    return a;
}
__device__ __forceinline__ void cpa16s(u32 dst, const void* src) {
    asm volatile("cp.async.ca.shared.global [%0], [%1], 16;\n" :: "r"(dst), "l"(src));
}
__device__ __forceinline__ void ldsm4(u32& r0, u32& r1, u32& r2, u32& r3, u32 a) {
    asm volatile("ldmatrix.sync.aligned.m8n8.x4.shared.b16 {%0,%1,%2,%3}, [%4];"
                 : "=r"(r0), "=r"(r1), "=r"(r2), "=r"(r3) : "r"(a));
}
__device__ __forceinline__ void ldsm2(u32& r0, u32& r1, u32 a) {
    asm volatile("ldmatrix.sync.aligned.m8n8.x2.shared.b16 {%0,%1}, [%2];"
                 : "=r"(r0), "=r"(r1) : "r"(a));
}
__device__ __forceinline__ void mma16816(float* c, const u32* a, const u32* bfr) {
    asm volatile(
        "mma.sync.aligned.m16n8k16.row.col.f32.f16.f16.f32 "
        "{%0,%1,%2,%3}, {%4,%5,%6,%7}, {%8,%9}, {%0,%1,%2,%3};"
        : "+f"(c[0]), "+f"(c[1]), "+f"(c[2]), "+f"(c[3])
        : "r"(a[0]), "r"(a[1]), "r"(a[2]), "r"(a[3]), "r"(bfr[0]), "r"(bfr[1]));
}

// ---------------------------------------------------------------------------
// Kernel 1: transpose image_feats [B,C,H,W] -> g_tfeat [B,H,W,C]
// ---------------------------------------------------------------------------
__global__ void transpose_kernel(const float* __restrict__ in)
{
    __shared__ float s[32][33];
    int tx = threadIdx.x, ty = threadIdx.y;
    int x0 = blockIdx.x * 32;
    int c0 = blockIdx.y * 32;
    int z  = blockIdx.z;
    int b = z >> 7, y = z & 127;
#pragma unroll
    for (int r = 0; r < 4; ++r) {
        int c = c0 + ty + r * 8;
        s[ty + r * 8][tx] = in[(((size_t)b * CCH + c) * FEAT_H + y) * FEAT_W + x0 + tx];
    }
    __syncthreads();
#pragma unroll
    for (int r = 0; r < 4; ++r) {
        int xo = ty + r * 8;
        g_tfeat[(((size_t)b * FEAT_H + y) * FEAT_W + x0 + xo) * CCH + c0 + tx] = s[tx][xo];
    }
}

// ---------------------------------------------------------------------------
// Kernel 2: fold depth-MLP into score-MLP hidden layer.
// ---------------------------------------------------------------------------
__global__ void prep_kernel(const float* __restrict__ dw2, const float* __restrict__ sw1,
                            const float* __restrict__ db2, const float* __restrict__ he,
                            const float* __restrict__ sb1)
{
    int j = threadIdx.x;
    int r = blockIdx.x;
    if (r < HID) {
        float a = 0.f;
        for (int c = 0; c < CCH; ++c) a = fmaf(dw2[r * CCH + c], sw1[c * HID + j], a);
        g_K1[r * HID + j] = a;
    } else {
        int h = r - HID;
        float a = sb1[j];
        for (int c = 0; c < CCH; ++c) a = fmaf(db2[c] + he[h * CCH + c], sw1[c * HID + j], a);
        g_C1[h * HID + j] = a;
    }
}

// ---------------------------------------------------------------------------
// Kernel 2b: sort relu knots (rank sort, 1 block x 64).
// ---------------------------------------------------------------------------
__global__ void prep_seg1_kernel(const float* __restrict__ dw1,
                                 const float* __restrict__ db1)
{
    __shared__ float tau[HID];
    int k = threadIdx.x;
    float dw = dw1[k];
    tau[k] = (dw != 0.f) ? (-db1[k] / dw) : 1e30f;
    __syncthreads();
    float mine = tau[k];
    int rank = 0;
    for (int j = 0; j < HID; ++j) {
        float o = tau[j];
        if (o < mine || (o == mine && j < k)) ++rank;
    }
    g_thr[rank] = mine;
}

// ---------------------------------------------------------------------------
// Kernel 2c: per-segment slope/intercept sums (grid 65, block 64).
// ---------------------------------------------------------------------------
__global__ void prep_seg2_kernel(const float* __restrict__ dw1,
                                 const float* __restrict__ db1)
{
    int s = blockIdx.x;
    int j = threadIdx.x;
    float lo = (s == 0) ? g_thr[0] - 1.0f : g_thr[s - 1];
    float hi = (s == 64) ? g_thr[63] + 1.0f : g_thr[s];
    float mid = 0.5f * lo + 0.5f * hi;
    float A = 0.f, B = 0.f;
    for (int k = 0; k < HID; ++k) {
        float dw = dw1[k], db = db1[k];
        if (fmaf(mid, dw, db) > 0.f) {
            float k1 = g_K1[k * HID + j];
            A = fmaf(dw, k1, A);
            B = fmaf(db, k1, B);
        }
    }
    g_segA[s * HID + j] = A;
    g_segB[s * HID + j] = B;
}

// ---------------------------------------------------------------------------
// Kernel W: prepack single-fp16 weights. K = channel (0..95), pad to 128.
// image [conv][ky*3+kx][slab]: 96 oc rows x 64 fp16, SW128 swizzled.
// ---------------------------------------------------------------------------
__global__ void prep_wpack_kernel(const float* __restrict__ w1,
                                  const float* __restrict__ w2)
{
    int blk = blockIdx.x;            // conv*18 + kk*2 + slab
    int conv = blk / 18;
    int r = blk % 18;
    int kk = r >> 1;
    int slab = r & 1;
    int ky = kk / 3, kx = kk % 3;
    const float* W = conv ? w2 : w1;
    unsigned char* img = g_wpack + (size_t)blk * W_IMG;

    for (int i = threadIdx.x; i < 96 * 64; i += 256) {
        int oc = i >> 6, k64 = i & 63;
        int K = slab * 64 + k64;
        __half val = __float2half_rn(
            (K < 96) ? W[(size_t)oc * 864 + K * 9 + ky * 3 + kx] : 0.f);
        u32 off = SW128((u32)(oc * 128 + k64 * 2));
        *(__half*)(img + off) = val;
    }
}

// ---------------------------------------------------------------------------
// Kernel 3: BEV lift — piecewise-linear depth MLP + token broadcast.
// Act store: single fp16 per channel; slab1 slots 32..63 stay zero.
// ---------------------------------------------------------------------------
__global__ void __launch_bounds__(256, 3)
lift_kernel(const float* __restrict__ l2i, const float* __restrict__ sw1,
            const float* __restrict__ sw2, const float* __restrict__ sb2p)
{
    extern __shared__ float sm[];
    float2* s_sw1 = (float2*)sm;              // 96*32 float2  (24576 B)
    float*  s_C1  = (float*)(s_sw1 + CCH * 32); // 192
    float*  s_sw2 = s_C1 + 192;               // 64
    float*  s_thr = s_sw2 + 64;               // 64
    float4* s_tok = (float4*)(s_thr + 64);    // 8 warps x 96 (12288 B)
    __half* s_act2 = (__half*)(s_tok + 8 * 96); // [2 slab][32 px][64] (8192 B)

    int tid = threadIdx.x;
    int w = tid >> 5, lane = tid & 31;
    int j0 = 2 * lane;
    float4* s_tokw = s_tok + w * 96;

    for (int i = tid; i < CCH * 32; i += 256) s_sw1[i] = ((const float2*)sw1)[i];
    if (tid < 192) s_C1[tid] = g_C1[tid];
    if (tid < 64) s_sw2[tid] = sw2[tid];
    if (tid < 64) s_thr[tid] = g_thr[tid];
    for (int i = tid; i < 2048; i += 256) ((u32*)s_act2)[i] = 0u;  // zero pad region
    __syncthreads();
    float sb2 = *sb2p;

    const int NTILES = NB * NCELL / 32;
    for (int tile = blockIdx.x; tile < NTILES; tile += gridDim.x) {
        int N0 = tile * 32;
        int b = (N0 >= NCELL) ? 1 : 0;
        int n0 = N0 - b * NCELL;
        int y = n0 / BEV;
        int x0 = n0 - y * BEV;

        const float* M = l2i + b * 16;
        float M00 = M[0], M01 = M[1], M02 = M[2],  M03 = M[3];
        float M10 = M[4], M11 = M[5], M12 = M[6],  M13 = M[7];
        float M20 = M[8], M21 = M[9], M22 = M[10], M23 = M[11];

        float py = ((float)y + 0.5f) / 320.0f * 102.4f - 51.2f;

        for (int cc = 0; cc < 4; ++cc) {
            int cj = w + cc * 8;
            int x = x0 + cj;
            float px = ((float)x + 0.5f) / 320.0f * 102.4f - 51.2f;
            float b0 = M00 * px + M01 * py + M03;
            float b1 = M10 * px + M11 * py + M13;
            float b2 = M20 * px + M21 * py + M23;

            float sv[3][3];
            float dd[3];
            bool  val[3];
            float lg[3];

#pragma unroll
            for (int h = 0; h < 3; ++h) {
                float fh = (float)h;
                float p0 = b0 + fh * M02;
                float p1 = b1 + fh * M12;
                float dep = b2 + fh * M22;
                float dn = fmaxf(dep, 1e-5f);
                float u = p0 / dn, v = p1 / dn;
                float gx = u / 351.0f * 2.0f - 1.0f;
                float gy = v / 127.0f * 2.0f - 1.0f;
                bool valid = (dep > 1e-3f) && (fabsf(gx) <= 1.0f) && (fabsf(gy) <= 1.0f);
                val[h] = valid;
                sv[0][h] = 0.f; sv[1][h] = 0.f; sv[2][h] = 0.f;
                dd[h] = 0.f;

                if (valid) {
                    float xs = (gx + 1.0f) * 0.5f * 351.0f;
                    float ys = (gy + 1.0f) * 0.5f * 127.0f;
                    float xf = floorf(xs), yf = floorf(ys);
                    float wx = xs - xf, wy = ys - yf;
                    int ix = (int)xf, iy = (int)yf;
                    int ix1 = ix + 1, iy1 = iy + 1;
                    float w00 = (1.f - wx) * (1.f - wy);
                    float w10 = wx * (1.f - wy);
                    float w01 = (1.f - wx) * wy;
                    float w11 = wx * wy;
                    if (ix1 > 351) { ix1 = 351; w10 = 0.f; w11 = 0.f; }
                    if (iy1 > 127) { iy1 = 127; w01 = 0.f; w11 = 0.f; }

                    int rowA = (b * FEAT_H + iy) * FEAT_W;
                    int rowB = (b * FEAT_H + iy1) * FEAT_W;
                    int o00 = (rowA + ix) * CCH + lane;
                    int o10 = (rowA + ix1) * CCH + lane;
                    int o01 = (rowB + ix) * CCH + lane;
                    int o11 = (rowB + ix1) * CCH + lane;
#pragma unroll
                    for (int k = 0; k < 3; ++k) {
                        float A  = g_tfeat[o00 + 32 * k];
                        float Bv = g_tfeat[o10 + 32 * k];
                        float Cv = g_tfeat[o01 + 32 * k];
                        float Dv = g_tfeat[o11 + 32 * k];
                        sv[k][h] = fmaf(w00, A, fmaf(w10, Bv, fmaf(w01, Cv, w11 * Dv)));
                    }
                    dd[h] = log1pf(fmaxf(dep, 1e-3f));
                }
            }

            bool anym = val[0] | val[1] | val[2];
            lg[0] = -INFINITY; lg[1] = -INFINITY; lg[2] = -INFINITY;

            if (anym) {   // warp-uniform
#pragma unroll
                for (int g = 0; g < 3; ++g)
                    s_tokw[g * 32 + lane] = make_float4(sv[g][0], sv[g][1], sv[g][2], 0.f);
                __syncwarp();

                int seg[3];
#pragma unroll
                for (int h = 0; h < 3; ++h) {
                    float d = dd[h];
                    int s = 0;
#pragma unroll
                    for (int off = 64; off > 0; off >>= 1) {
                        int t = s + off;
                        if (t <= 64 && s_thr[t - 1] <= d) s = t;
                    }
                    seg[h] = s;
                }
                float2 A0 = ((const float2*)(g_segA + seg[0] * HID))[lane];
                float2 B0 = ((const float2*)(g_segB + seg[0] * HID))[lane];
                float2 A1 = ((const float2*)(g_segA + seg[1] * HID))[lane];
                float2 B1 = ((const float2*)(g_segB + seg[1] * HID))[lane];
                float2 A2 = ((const float2*)(g_segA + seg[2] * HID))[lane];
                float2 B2 = ((const float2*)(g_segB + seg[2] * HID))[lane];

                float a00 = s_C1[j0]       + fmaf(A0.x, dd[0], B0.x);
                float a01 = s_C1[j0 + 1]   + fmaf(A0.y, dd[0], B0.y);
                float a10 = s_C1[64 + j0]  + fmaf(A1.x, dd[1], B1.x);
                float a11 = s_C1[64 + j0 + 1] + fmaf(A1.y, dd[1], B1.y);
                float a20 = s_C1[128 + j0] + fmaf(A2.x, dd[2], B2.x);
                float a21 = s_C1[128 + j0 + 1] + fmaf(A2.y, dd[2], B2.y);

#pragma unroll 8
                for (int c = 0; c < CCH; ++c) {
                    float4 t = s_tokw[c];
                    float2 ww = s_sw1[c * 32 + lane];
                    a00 = fmaf(t.x, ww.x, a00); a01 = fmaf(t.x, ww.y, a01);
                    a10 = fmaf(t.y, ww.x, a10); a11 = fmaf(t.y, ww.y, a11);
                    a20 = fmaf(t.z, ww.x, a20); a21 = fmaf(t.z, ww.y, a21);
                }

                float swa = s_sw2[j0], swb = s_sw2[j0 + 1];
                float p0 = fmaxf(a00, 0.f) * swa + fmaxf(a01, 0.f) * swb;
                float p1 = fmaxf(a10, 0.f) * swa + fmaxf(a11, 0.f) * swb;
                float p2 = fmaxf(a20, 0.f) * swa + fmaxf(a21, 0.f) * swb;
#pragma unroll
                for (int off = 16; off > 0; off >>= 1) {
                    p0 += __shfl_xor_sync(0xffffffffu, p0, off);
                    p1 += __shfl_xor_sync(0xffffffffu, p1, off);
                    p2 += __shfl_xor_sync(0xffffffffu, p2, off);
                }
                if (val[0]) lg[0] = p0 + sb2;
                if (val[1]) lg[1] = p1 + sb2;
                if (val[2]) lg[2] = p2 + sb2;
                __syncwarp();
            }

            float m = fmaxf(fmaxf(lg[0], lg[1]), lg[2]);
            float e0 = 0.f, e1 = 0.f, e2 = 0.f;
            if (m > -1e30f) {
                e0 = expf(lg[0] - m);
                e1 = expf(lg[1] - m);
                e2 = expf(lg[2] - m);
                float inv = 1.0f / (e0 + e1 + e2);
                e0 *= inv; e1 *= inv; e2 *= inv;
            }
            // channel c = lane + 32*g -> slab c>>6, slot c&63 (single fp16)
#pragma unroll
            for (int g = 0; g < 3; ++g) {
                float f = sv[g][0] * e0 + sv[g][1] * e1 + sv[g][2] * e2;
                int c = lane + 32 * g;
                s_act2[(c >> 6) * 2048 + cj * 64 + (c & 63)] = __float2half_rn(f);
            }
        }
        __syncthreads();
        {
            size_t rowb = ((size_t)b * 322 + y + 1) * NSLAB;
            const uint4* src = (const uint4*)s_act2;
            for (int i = tid; i < 512; i += 256) {
                int slab = i >> 8;
                int rem = i & 255;
                int p = rem >> 3, ch = rem & 7;
                uint4 v = src[slab * 256 + p * 8 + ch];
                *(uint4*)((char*)g_act0 + ((rowb + slab) * 328 + x0 + p + 1) * 128 + ch * 16) = v;
            }
        }
        __syncthreads();
    }
}

// ---------------------------------------------------------------------------
// Kernel C<PHASE>: mma.sync fp16 conv, K=128 (6 rounds). 256 thr, warp=96x40.
// ---------------------------------------------------------------------------
template <int PHASE>
__global__ void __launch_bounds__(256, 1)
mma_conv_kernel(const float* __restrict__ gg, const float* __restrict__ bb_,
                const float* __restrict__ mm, const float* __restrict__ vv,
                float* __restrict__ outp)
{
    extern __shared__ __align__(128) char smc[];
    u32 base = smem_u32(smc);
    u32 actb2[2] = { base, base + ACT_SZ };
    u32 wb2[2]   = { base + 2 * ACT_SZ, base + 2 * ACT_SZ + W_SZ };

    const __half* srcAct = PHASE ? g_act1 : g_act0;

    int tid = threadIdx.x, wid = tid >> 5, lane = tid & 31;
    int rowid = blockIdx.x;
    int b = rowid / 320, y = rowid % 320;
    int wpx = wid * 40;
    int l7 = lane & 7, g = lane >> 3;

    float acc[6][5][4];
#pragma unroll
    for (int mi = 0; mi < 6; ++mi)
#pragma unroll
        for (int nt = 0; nt < 5; ++nt)
#pragma unroll
            for (int c = 0; c < 4; ++c) acc[mi][nt][c] = 0.f;

    auto stage = [&](int r, int bufi) {
        int ky = r >> 1, slab = r & 1;
        const char* asrc = (const char*)srcAct +
            (((size_t)b * 322 + y + ky) * NSLAB + slab) * 328 * 128;
        for (int idx = tid; idx < 2624; idx += 256) {
            int px = idx >> 3, ch = idx & 7;
            cpa16s(actb2[bufi] + px * 128 + ((ch * 16) ^ ((px & 7) << 4)),
                   asrc + (size_t)px * 128 + ch * 16);
        }
        const unsigned char* wsrc = g_wpack +
            (size_t)(((PHASE * 9 + ky * 3) * NSLAB) + slab) * W_IMG;
        for (int idx = tid; idx < 2304; idx += 256) {
            int c = idx / 768, j = idx - c * 768;
            cpa16s(wb2[bufi] + c * W_IMG + j * 16,
                   wsrc + (size_t)c * NSLAB * W_IMG + j * 16);
        }
        asm volatile("cp.async.commit_group;\n");
    };

    stage(0, 0);

    for (int r = 0; r < 6; ++r) {
        int bufi = r & 1;
        if (r + 1 < 6) {
            stage(r + 1, bufi ^ 1);
            asm volatile("cp.async.wait_group 1;\n");
        } else {
            asm volatile("cp.async.wait_group 0;\n");
        }
        __syncthreads();

        u32 actbuf = actb2[bufi];
#pragma unroll
        for (int kx = 0; kx < 3; ++kx) {
            u32 wimg = wb2[bufi] + kx * W_IMG;
#pragma unroll
            for (int kk = 0; kk < 4; ++kk) {
                int kc2 = 2 * kk;
                u32 af[6][4];
                {
                    int arow_off = ((g & 1) << 3) + l7;
                    int achunk = kc2 + (g >> 1);
                    u32 axor = (u32)(achunk * 16) ^ ((u32)l7 << 4);
#pragma unroll
                    for (int mi = 0; mi < 6; ++mi) {
                        u32 a = wimg + (mi * 16 + arow_off) * 128 + axor;
                        ldsm4(af[mi][0], af[mi][1], af[mi][2], af[mi][3], a);
                    }
                }
                u32 bf[5][2];
                {
                    int px0 = wpx + kx + ((g >> 1) << 3) + l7;
                    int chunk = kc2 + (g & 1);
                    u32 a0 = actbuf + px0 * 128 + (((u32)(chunk * 16)) ^ (((u32)px0 & 7) << 4));
                    ldsm4(bf[0][0], bf[0][1], bf[1][0], bf[1][1], a0);
                    int px1 = px0 + 16;
                    u32 a1 = actbuf + px1 * 128 + (((u32)(chunk * 16)) ^ (((u32)px1 & 7) << 4));
                    ldsm4(bf[2][0], bf[2][1], bf[3][0], bf[3][1], a1);
                    int px2 = wpx + kx + 32 + l7;
                    int ch2 = kc2 + (g & 1);
                    u32 a2 = actbuf + px2 * 128 + (((u32)(ch2 * 16)) ^ (((u32)px2 & 7) << 4));
                    ldsm2(bf[4][0], bf[4][1], a2);
                }
#pragma unroll
                for (int mi = 0; mi < 6; ++mi)
#pragma unroll
                    for (int nt = 0; nt < 5; ++nt)
                        mma16816(acc[mi][nt], af[mi], bf[nt]);
            }
        }
        __syncthreads();
    }

    // ---- epilogue: BN + ReLU ----
    int lrow = lane >> 2;
    int lcol = (lane & 3) * 2;

    if (PHASE == 0) {
        __half* s_ep = (__half*)smc;     // [2 slab][320 px][64 slot]
        // zero pad region: slab1 slots 32..63
        for (int idx = tid; idx < 5120; idx += 256) {
            int p = idx >> 4, sl = idx & 15;
            ((u32*)s_ep)[10240 + p * 32 + 16 + sl] = 0u;
        }
        __syncthreads();
#pragma unroll
        for (int mi = 0; mi < 6; ++mi) {
            int oc0 = mi * 16 + lrow;
            int oc1 = oc0 + 8;
            float a0 = gg[oc0] * rsqrtf(vv[oc0] + 1e-3f);
            float e0 = bb_[oc0] - mm[oc0] * a0;
            float a1 = gg[oc1] * rsqrtf(vv[oc1] + 1e-3f);
            float e1 = bb_[oc1] - mm[oc1] * a1;
            int s0 = (oc0 >> 6) * 20480 + (oc0 & 63);
            int s1 = (oc1 >> 6) * 20480 + (oc1 & 63);
#pragma unroll
            for (int nt = 0; nt < 5; ++nt) {
                int px = wpx + nt * 8 + lcol;
                s_ep[s0 + px * 64]        = __float2half_rn(fmaxf(fmaf(acc[mi][nt][0], a0, e0), 0.f));
                s_ep[s0 + (px + 1) * 64]  = __float2half_rn(fmaxf(fmaf(acc[mi][nt][1], a0, e0), 0.f));
                s_ep[s1 + px * 64]        = __float2half_rn(fmaxf(fmaf(acc[mi][nt][2], a1, e1), 0.f));
                s_ep[s1 + (px + 1) * 64]  = __float2half_rn(fmaxf(fmaf(acc[mi][nt][3], a1, e1), 0.f));
            }
        }
        __syncthreads();
        const uint4* src = (const uint4*)s_ep;
        size_t rowb = ((size_t)b * 322 + y + 1) * NSLAB;
        for (int idx = tid; idx < 5120; idx += 256) {
            int slab = idx / 2560;
            int rem = idx - slab * 2560;
            int p = rem >> 3, ch = rem & 7;
            uint4 v = src[slab * 2560 + p * 8 + ch];
            *(uint4*)((char*)g_act1 + ((rowb + slab) * 328 + p + 1) * 128 + ch * 16) = v;
        }
    } else {
#pragma unroll
        for (int mi = 0; mi < 6; ++mi) {
            int oc0 = mi * 16 + lrow;
            int oc1 = oc0 + 8;
            float a0 = gg[oc0] * rsqrtf(vv[oc0] + 1e-3f);
            float e0 = bb_[oc0] - mm[oc0] * a0;
            float a1 = gg[oc1] * rsqrtf(vv[oc1] + 1e-3f);
            float e1 = bb_[oc1] - mm[oc1] * a1;
#pragma unroll
            for (int nt = 0; nt < 5; ++nt) {
                int px = wpx + nt * 8 + lcol;
                float v00 = fmaxf(fmaf(acc[mi][nt][0], a0, e0), 0.f);
                float v01 = fmaxf(fmaf(acc[mi][nt][1], a0, e0), 0.f);
                float v10 = fmaxf(fmaf(acc[mi][nt][2], a1, e1), 0.f);
                float v11 = fmaxf(fmaf(acc[mi][nt][3], a1, e1), 0.f);
                *reinterpret_cast<float2*>(
                    &outp[((size_t)(b * CCH + oc0) * BEV + y) * BEV + px]) =
                    make_float2(v00, v01);
                *reinterpret_cast<float2*>(
                    &outp[((size_t)(b * CCH + oc1) * BEV + y) * BEV + px]) =
                    make_float2(v10, v11);
            }
        }
    }
}

// ---------------------------------------------------------------------------
// Launch
// ---------------------------------------------------------------------------
extern "C" void kernel_launch(void* const* d_in, const int* in_sizes, int n_in,
                              void* d_out, int out_size)
{
    const float* feats = (const float*)d_in[0];
    const float* l2i   = (const float*)d_in[1];
    const float* he    = (const float*)d_in[2];
    const float* dw1   = (const float*)d_in[3];
    const float* db1   = (const float*)d_in[4];
    const float* dw2   = (const float*)d_in[5];
    const float* db2   = (const float*)d_in[6];
    const float* sw1   = (const float*)d_in[7];
    const float* sb1   = (const float*)d_in[8];
    const float* sw2   = (const float*)d_in[9];
    const float* sb2   = (const float*)d_in[10];
    const float* c1w   = (const float*)d_in[11];
    const float* b1g   = (const float*)d_in[12];
    const float* b1b   = (const float*)d_in[13];
    const float* b1m   = (const float*)d_in[14];
    const float* b1v   = (const float*)d_in[15];
    const float* c2w   = (const float*)d_in[16];
    const float* b2g   = (const float*)d_in[17];
    const float* b2b   = (const float*)d_in[18];
    const float* b2m   = (const float*)d_in[19];
    const float* b2v   = (const float*)d_in[20];
    float* out = (float*)d_out;

    transpose_kernel<<<dim3(11, 3, NB * FEAT_H), dim3(32, 8)>>>(feats);
    prep_kernel<<<HID + 3, HID>>>(dw2, sw1, db2, he, sb1);
    prep_seg1_kernel<<<1, HID>>>(dw1, db1);
    prep_seg2_kernel<<<65, HID>>>(dw1, db1);
    prep_wpack_kernel<<<36, 256>>>(c1w, c2w);

    // lift smem: sw1 + C1 + sw2 + thr + tok + act2
    size_t lsm = (size_t)(CCH * 32) * 8 + (192 + 64 + 64) * 4 +
                 (size_t)8 * 96 * 16 + 2 * 32 * 64 * 2;
    cudaFuncSetAttribute(lift_kernel, cudaFuncAttributeMaxDynamicSharedMemorySize, (int)lsm);
    lift_kernel<<<444, 256, lsm>>>(l2i, sw1, sw2, sb2);

    size_t csm = 2 * ACT_SZ + 2 * W_SZ;   // 157,696 B
    cudaFuncSetAttribute(mma_conv_kernel<0>, cudaFuncAttributeMaxDynamicSharedMemorySize, (int)csm);
    cudaFuncSetAttribute(mma_conv_kernel<1>, cudaFuncAttributeMaxDynamicSharedMemorySize, (int)csm);

    mma_conv_kernel<0><<<NB * BEV, 256, csm>>>(b1g, b1b, b1m, b1v, out);
    mma_conv_kernel<1><<<NB * BEV, 256, csm>>>(b2g, b2b, b2m, b2v, out);
}

// round 17
// speedup vs baseline: 1.4918x; 1.0924x over previous
#include <cuda_runtime.h>
#include <cuda_bf16.h>
#include <cuda_fp16.h>
#include <math.h>
#include <stdint.h>

typedef unsigned long long ull;
typedef unsigned int u32;

// ---------------------------------------------------------------------------
// Problem constants
// ---------------------------------------------------------------------------
#define BEV 320
#define NCELL (BEV*BEV)
#define FEAT_H 128
#define FEAT_W 352
#define CCH 96
#define HID 64
#define NB 2

// conv-as-GEMM: single-fp16 weights, K = 96 real (slab0: 64 ch, slab1: 32 ch).
// act rows: [b][y 322][slab 2][px 328][64 fp16]; slab1 uses slots 0..31 only.
#define NSLAB 2
#define W_IMG 12288        // weight slab image: 96 oc rows x 64 fp16 (128B rows)
#define ACT_SZ (328*128)   // one act slab row in smem
#define W_SZ (3*W_IMG)     // 3 kx images per round

#define SW128(o) ((o) ^ (((o) >> 3) & 0x70))

// ---------------------------------------------------------------------------
// Scratch
// ---------------------------------------------------------------------------
__device__ __align__(16) float g_tfeat[NB * FEAT_H * FEAT_W * CCH];
__device__ float g_K1[HID * HID];
__device__ float g_C1[3 * HID];
// piecewise-linear depth-MLP tables
__device__ float g_thr[HID];
__device__ __align__(16) float g_segA[65 * HID];
__device__ __align__(16) float g_segB[65 * HID];
// prepacked weight images: [conv 2][ky*3+kx 9][slab 2][12288 B], swizzled
__device__ __align__(16) unsigned char g_wpack[2 * 9 * NSLAB * W_IMG];
// fp16 act rows
__device__ __align__(16) __half g_act0[(size_t)NB * 322 * NSLAB * 328 * 64];
__device__ __align__(16) __half g_act1[(size_t)NB * 322 * NSLAB * 328 * 64];

// ---------------------------------------------------------------------------
// Helpers
// ---------------------------------------------------------------------------
__device__ __forceinline__ u32 smem_u32(const void* p) {
    u32 a;
    asm("{ .reg .u64 t; cvta.to.shared.u64 t, %1; cvt.u32.u64 %0, t; }" : "=r"(a) : "l"(p));
    return a;
}
__device__ __forceinline__ void cpa16s(u32 dst, const void* src) {
    asm volatile("cp.async.ca.shared.global [%0], [%1], 16;\n" :: "r"(dst), "l"(src));
}
__device__ __forceinline__ void ldsm4(u32& r0, u32& r1, u32& r2, u32& r3, u32 a) {
    asm volatile("ldmatrix.sync.aligned.m8n8.x4.shared.b16 {%0,%1,%2,%3}, [%4];"
                 : "=r"(r0), "=r"(r1), "=r"(r2), "=r"(r3) : "r"(a));
}
__device__ __forceinline__ void ldsm2(u32& r0, u32& r1, u32 a) {
    asm volatile("ldmatrix.sync.aligned.m8n8.x2.shared.b16 {%0,%1}, [%2];"
                 : "=r"(r0), "=r"(r1) : "r"(a));
}
__device__ __forceinline__ void mma16816(float* c, const u32* a, const u32* bfr) {
    asm volatile(
        "mma.sync.aligned.m16n8k16.row.col.f32.f16.f16.f32 "
        "{%0,%1,%2,%3}, {%4,%5,%6,%7}, {%8,%9}, {%0,%1,%2,%3};"
        : "+f"(c[0]), "+f"(c[1]), "+f"(c[2]), "+f"(c[3])
        : "r"(a[0]), "r"(a[1]), "r"(a[2]), "r"(a[3]), "r"(bfr[0]), "r"(bfr[1]));
}

// ---------------------------------------------------------------------------
// Kernel 1: transpose image_feats [B,C,H,W] -> g_tfeat [B,H,W,C]
// ---------------------------------------------------------------------------
__global__ void transpose_kernel(const float* __restrict__ in)
{
    __shared__ float s[32][33];
    int tx = threadIdx.x, ty = threadIdx.y;
    int x0 = blockIdx.x * 32;
    int c0 = blockIdx.y * 32;
    int z  = blockIdx.z;
    int b = z >> 7, y = z & 127;
#pragma unroll
    for (int r = 0; r < 4; ++r) {
        int c = c0 + ty + r * 8;
        s[ty + r * 8][tx] = in[(((size_t)b * CCH + c) * FEAT_H + y) * FEAT_W + x0 + tx];
    }
    __syncthreads();
#pragma unroll
    for (int r = 0; r < 4; ++r) {
        int xo = ty + r * 8;
        g_tfeat[(((size_t)b * FEAT_H + y) * FEAT_W + x0 + xo) * CCH + c0 + tx] = s[tx][xo];
    }
}

// ---------------------------------------------------------------------------
// Kernel 2: fold depth-MLP into score-MLP hidden layer.
// ---------------------------------------------------------------------------
__global__ void prep_kernel(const float* __restrict__ dw2, const float* __restrict__ sw1,
                            const float* __restrict__ db2, const float* __restrict__ he,
                            const float* __restrict__ sb1)
{
    int j = threadIdx.x;
    int r = blockIdx.x;
    if (r < HID) {
        float a = 0.f;
        for (int c = 0; c < CCH; ++c) a = fmaf(dw2[r * CCH + c], sw1[c * HID + j], a);
        g_K1[r * HID + j] = a;
    } else {
        int h = r - HID;
        float a = sb1[j];
        for (int c = 0; c < CCH; ++c) a = fmaf(db2[c] + he[h * CCH + c], sw1[c * HID + j], a);
        g_C1[h * HID + j] = a;
    }
}

// ---------------------------------------------------------------------------
// Kernel 2b: sort relu knots (rank sort, 1 block x 64).
// ---------------------------------------------------------------------------
__global__ void prep_seg1_kernel(const float* __restrict__ dw1,
                                 const float* __restrict__ db1)
{
    __shared__ float tau[HID];
    int k = threadIdx.x;
    float dw = dw1[k];
    tau[k] = (dw != 0.f) ? (-db1[k] / dw) : 1e30f;
    __syncthreads();
    float mine = tau[k];
    int rank = 0;
    for (int j = 0; j < HID; ++j) {
        float o = tau[j];
        if (o < mine || (o == mine && j < k)) ++rank;
    }
    g_thr[rank] = mine;
}

// ---------------------------------------------------------------------------
// Kernel 2c: per-segment slope/intercept sums (grid 65, block 64).
// ---------------------------------------------------------------------------
__global__ void prep_seg2_kernel(const float* __restrict__ dw1,
                                 const float* __restrict__ db1)
{
    int s = blockIdx.x;
    int j = threadIdx.x;
    float lo = (s == 0) ? g_thr[0] - 1.0f : g_thr[s - 1];
    float hi = (s == 64) ? g_thr[63] + 1.0f : g_thr[s];
    float mid = 0.5f * lo + 0.5f * hi;
    float A = 0.f, B = 0.f;
    for (int k = 0; k < HID; ++k) {
        float dw = dw1[k], db = db1[k];
        if (fmaf(mid, dw, db) > 0.f) {
            float k1 = g_K1[k * HID + j];
            A = fmaf(dw, k1, A);
            B = fmaf(db, k1, B);
        }
    }
    g_segA[s * HID + j] = A;
    g_segB[s * HID + j] = B;
}

// ---------------------------------------------------------------------------
// Kernel W: prepack single-fp16 weights. K = channel (0..95).
// ---------------------------------------------------------------------------
__global__ void prep_wpack_kernel(const float* __restrict__ w1,
                                  const float* __restrict__ w2)
{
    int blk = blockIdx.x;            // conv*18 + kk*2 + slab
    int conv = blk / 18;
    int r = blk % 18;
    int kk = r >> 1;
    int slab = r & 1;
    int ky = kk / 3, kx = kk % 3;
    const float* W = conv ? w2 : w1;
    unsigned char* img = g_wpack + (size_t)blk * W_IMG;

    for (int i = threadIdx.x; i < 96 * 64; i += 256) {
        int oc = i >> 6, k64 = i & 63;
        int K = slab * 64 + k64;
        __half val = __float2half_rn(
            (K < 96) ? W[(size_t)oc * 864 + K * 9 + ky * 3 + kx] : 0.f);
        u32 off = SW128((u32)(oc * 128 + k64 * 2));
        *(__half*)(img + off) = val;
    }
}

// ---------------------------------------------------------------------------
// Kernel 3: BEV lift — piecewise-linear depth MLP + token broadcast.
// ---------------------------------------------------------------------------
__global__ void __launch_bounds__(256, 3)
lift_kernel(const float* __restrict__ l2i, const float* __restrict__ sw1,
            const float* __restrict__ sw2, const float* __restrict__ sb2p)
{
    extern __shared__ float sm[];
    float2* s_sw1 = (float2*)sm;              // 96*32 float2  (24576 B)
    float*  s_C1  = (float*)(s_sw1 + CCH * 32); // 192
    float*  s_sw2 = s_C1 + 192;               // 64
    float*  s_thr = s_sw2 + 64;               // 64
    float4* s_tok = (float4*)(s_thr + 64);    // 8 warps x 96 (12288 B)
    __half* s_act2 = (__half*)(s_tok + 8 * 96); // [2 slab][32 px][64] (8192 B)

    int tid = threadIdx.x;
    int w = tid >> 5, lane = tid & 31;
    int j0 = 2 * lane;
    float4* s_tokw = s_tok + w * 96;

    for (int i = tid; i < CCH * 32; i += 256) s_sw1[i] = ((const float2*)sw1)[i];
    if (tid < 192) s_C1[tid] = g_C1[tid];
    if (tid < 64) s_sw2[tid] = sw2[tid];
    if (tid < 64) s_thr[tid] = g_thr[tid];
    __syncthreads();
    float sb2 = *sb2p;

    const int NTILES = NB * NCELL / 32;
    for (int tile = blockIdx.x; tile < NTILES; tile += gridDim.x) {
        int N0 = tile * 32;
        int b = (N0 >= NCELL) ? 1 : 0;
        int n0 = N0 - b * NCELL;
        int y = n0 / BEV;
        int x0 = n0 - y * BEV;

        const float* M = l2i + b * 16;
        float M00 = M[0], M01 = M[1], M02 = M[2],  M03 = M[3];
        float M10 = M[4], M11 = M[5], M12 = M[6],  M13 = M[7];
        float M20 = M[8], M21 = M[9], M22 = M[10], M23 = M[11];

        float py = ((float)y + 0.5f) / 320.0f * 102.4f - 51.2f;

        for (int cc = 0; cc < 4; ++cc) {
            int cj = w + cc * 8;
            int x = x0 + cj;
            float px = ((float)x + 0.5f) / 320.0f * 102.4f - 51.2f;
            float b0 = M00 * px + M01 * py + M03;
            float b1 = M10 * px + M11 * py + M13;
            float b2 = M20 * px + M21 * py + M23;

            float sv[3][3];
            float dd[3];
            bool  val[3];
            float lg[3];

#pragma unroll
            for (int h = 0; h < 3; ++h) {
                float fh = (float)h;
                float p0 = b0 + fh * M02;
                float p1 = b1 + fh * M12;
                float dep = b2 + fh * M22;
                float dn = fmaxf(dep, 1e-5f);
                float u = p0 / dn, v = p1 / dn;
                float gx = u / 351.0f * 2.0f - 1.0f;
                float gy = v / 127.0f * 2.0f - 1.0f;
                bool valid = (dep > 1e-3f) && (fabsf(gx) <= 1.0f) && (fabsf(gy) <= 1.0f);
                val[h] = valid;
                sv[0][h] = 0.f; sv[1][h] = 0.f; sv[2][h] = 0.f;
                dd[h] = 0.f;

                if (valid) {
                    float xs = (gx + 1.0f) * 0.5f * 351.0f;
                    float ys = (gy + 1.0f) * 0.5f * 127.0f;
                    float xf = floorf(xs), yf = floorf(ys);
                    float wx = xs - xf, wy = ys - yf;
                    int ix = (int)xf, iy = (int)yf;
                    int ix1 = ix + 1, iy1 = iy + 1;
                    float w00 = (1.f - wx) * (1.f - wy);
                    float w10 = wx * (1.f - wy);
                    float w01 = (1.f - wx) * wy;
                    float w11 = wx * wy;
                    if (ix1 > 351) { ix1 = 351; w10 = 0.f; w11 = 0.f; }
                    if (iy1 > 127) { iy1 = 127; w01 = 0.f; w11 = 0.f; }

                    int rowA = (b * FEAT_H + iy) * FEAT_W;
                    int rowB = (b * FEAT_H + iy1) * FEAT_W;
                    int o00 = (rowA + ix) * CCH + lane;
                    int o10 = (rowA + ix1) * CCH + lane;
                    int o01 = (rowB + ix) * CCH + lane;
                    int o11 = (rowB + ix1) * CCH + lane;
#pragma unroll
                    for (int k = 0; k < 3; ++k) {
                        float A  = g_tfeat[o00 + 32 * k];
                        float Bv = g_tfeat[o10 + 32 * k];
                        float Cv = g_tfeat[o01 + 32 * k];
                        float Dv = g_tfeat[o11 + 32 * k];
                        sv[k][h] = fmaf(w00, A, fmaf(w10, Bv, fmaf(w01, Cv, w11 * Dv)));
                    }
                    dd[h] = log1pf(fmaxf(dep, 1e-3f));
                }
            }

            bool anym = val[0] | val[1] | val[2];
            lg[0] = -INFINITY; lg[1] = -INFINITY; lg[2] = -INFINITY;

            if (anym) {   // warp-uniform
#pragma unroll
                for (int g = 0; g < 3; ++g)
                    s_tokw[g * 32 + lane] = make_float4(sv[g][0], sv[g][1], sv[g][2], 0.f);
                __syncwarp();

                int seg[3];
#pragma unroll
                for (int h = 0; h < 3; ++h) {
                    float d = dd[h];
                    int s = 0;
#pragma unroll
                    for (int off = 64; off > 0; off >>= 1) {
                        int t = s + off;
                        if (t <= 64 && s_thr[t - 1] <= d) s = t;
                    }
                    seg[h] = s;
                }
                float2 A0 = ((const float2*)(g_segA + seg[0] * HID))[lane];
                float2 B0 = ((const float2*)(g_segB + seg[0] * HID))[lane];
                float2 A1 = ((const float2*)(g_segA + seg[1] * HID))[lane];
                float2 B1 = ((const float2*)(g_segB + seg[1] * HID))[lane];
                float2 A2 = ((const float2*)(g_segA + seg[2] * HID))[lane];
                float2 B2 = ((const float2*)(g_segB + seg[2] * HID))[lane];

                float a00 = s_C1[j0]       + fmaf(A0.x, dd[0], B0.x);
                float a01 = s_C1[j0 + 1]   + fmaf(A0.y, dd[0], B0.y);
                float a10 = s_C1[64 + j0]  + fmaf(A1.x, dd[1], B1.x);
                float a11 = s_C1[64 + j0 + 1] + fmaf(A1.y, dd[1], B1.y);
                float a20 = s_C1[128 + j0] + fmaf(A2.x, dd[2], B2.x);
                float a21 = s_C1[128 + j0 + 1] + fmaf(A2.y, dd[2], B2.y);

#pragma unroll 8
                for (int c = 0; c < CCH; ++c) {
                    float4 t = s_tokw[c];
                    float2 ww = s_sw1[c * 32 + lane];
                    a00 = fmaf(t.x, ww.x, a00); a01 = fmaf(t.x, ww.y, a01);
                    a10 = fmaf(t.y, ww.x, a10); a11 = fmaf(t.y, ww.y, a11);
                    a20 = fmaf(t.z, ww.x, a20); a21 = fmaf(t.z, ww.y, a21);
                }

                float swa = s_sw2[j0], swb = s_sw2[j0 + 1];
                float p0 = fmaxf(a00, 0.f) * swa + fmaxf(a01, 0.f) * swb;
                float p1 = fmaxf(a10, 0.f) * swa + fmaxf(a11, 0.f) * swb;
                float p2 = fmaxf(a20, 0.f) * swa + fmaxf(a21, 0.f) * swb;
#pragma unroll
                for (int off = 16; off > 0; off >>= 1) {
                    p0 += __shfl_xor_sync(0xffffffffu, p0, off);
                    p1 += __shfl_xor_sync(0xffffffffu, p1, off);
                    p2 += __shfl_xor_sync(0xffffffffu, p2, off);
                }
                if (val[0]) lg[0] = p0 + sb2;
                if (val[1]) lg[1] = p1 + sb2;
                if (val[2]) lg[2] = p2 + sb2;
                __syncwarp();
            }

            float m = fmaxf(fmaxf(lg[0], lg[1]), lg[2]);
            float e0 = 0.f, e1 = 0.f, e2 = 0.f;
            if (m > -1e30f) {
                e0 = expf(lg[0] - m);
                e1 = expf(lg[1] - m);
                e2 = expf(lg[2] - m);
                float inv = 1.0f / (e0 + e1 + e2);
                e0 *= inv; e1 *= inv; e2 *= inv;
            }
#pragma unroll
            for (int g = 0; g < 3; ++g) {
                float f = sv[g][0] * e0 + sv[g][1] * e1 + sv[g][2] * e2;
                int c = lane + 32 * g;
                s_act2[(c >> 6) * 2048 + cj * 64 + (c & 63)] = __float2half_rn(f);
            }
        }
        __syncthreads();
        {
            size_t rowb = ((size_t)b * 322 + y + 1) * NSLAB;
            const uint4* src = (const uint4*)s_act2;
            // slab0: 32 px x 8 chunks; slab1: 32 px x 4 chunks (ch 0..3 only)
            for (int i = tid; i < 384; i += 256) {
                int slab, p, ch;
                if (i < 256) { slab = 0; p = i >> 3; ch = i & 7; }
                else { slab = 1; int rem = i - 256; p = rem >> 2; ch = rem & 3; }
                uint4 v = src[slab * 256 + p * 8 + ch];
                *(uint4*)((char*)g_act0 + ((rowb + slab) * 328 + x0 + p + 1) * 128 + ch * 16) = v;
            }
        }
        __syncthreads();
    }
}

// ---------------------------------------------------------------------------
// Kernel C<PHASE>: mma.sync fp16 conv, K=96 (slab0: 4 chunks, slab1: 2).
// 256 thr, warp = 96 oc x 40 px.
// ---------------------------------------------------------------------------
template <int PHASE>
__global__ void __launch_bounds__(256, 1)
mma_conv_kernel(const float* __restrict__ gg, const float* __restrict__ bb_,
                const float* __restrict__ mm, const float* __restrict__ vv,
                float* __restrict__ outp)
{
    extern __shared__ __align__(128) char smc[];
    u32 base = smem_u32(smc);
    u32 actb2[2] = { base, base + ACT_SZ };
    u32 wb2[2]   = { base + 2 * ACT_SZ, base + 2 * ACT_SZ + W_SZ };

    const __half* srcAct = PHASE ? g_act1 : g_act0;

    int tid = threadIdx.x, wid = tid >> 5, lane = tid & 31;
    int rowid = blockIdx.x;
    int b = rowid / 320, y = rowid % 320;
    int wpx = wid * 40;
    int l7 = lane & 7, g = lane >> 3;

    float acc[6][5][4];
#pragma unroll
    for (int mi = 0; mi < 6; ++mi)
#pragma unroll
        for (int nt = 0; nt < 5; ++nt)
#pragma unroll
            for (int c = 0; c < 4; ++c) acc[mi][nt][c] = 0.f;

    auto stage = [&](int r, int bufi) {
        int ky = r >> 1, slab = r & 1;
        const char* asrc = (const char*)srcAct +
            (((size_t)b * 322 + y + ky) * NSLAB + slab) * 328 * 128;
        if (slab == 0) {
            for (int idx = tid; idx < 2624; idx += 256) {
                int px = idx >> 3, ch = idx & 7;
                cpa16s(actb2[bufi] + px * 128 + ((ch * 16) ^ ((px & 7) << 4)),
                       asrc + (size_t)px * 128 + ch * 16);
            }
        } else {
            for (int idx = tid; idx < 1312; idx += 256) {
                int px = idx >> 2, ch = idx & 3;
                cpa16s(actb2[bufi] + px * 128 + ((ch * 16) ^ ((px & 7) << 4)),
                       asrc + (size_t)px * 128 + ch * 16);
            }
        }
        const unsigned char* wsrc = g_wpack +
            (size_t)(((PHASE * 9 + ky * 3) * NSLAB) + slab) * W_IMG;
        for (int idx = tid; idx < 2304; idx += 256) {
            int c = idx / 768, j = idx - c * 768;
            cpa16s(wb2[bufi] + c * W_IMG + j * 16,
                   wsrc + (size_t)c * NSLAB * W_IMG + j * 16);
        }
        asm volatile("cp.async.commit_group;\n");
    };

    stage(0, 0);

    for (int r = 0; r < 6; ++r) {
        int bufi = r & 1;
        if (r + 1 < 6) {
            stage(r + 1, bufi ^ 1);
            asm volatile("cp.async.wait_group 1;\n");
        } else {
            asm volatile("cp.async.wait_group 0;\n");
        }
        __syncthreads();

        u32 actbuf = actb2[bufi];
        auto chunk_body = [&](int kx, int kk) {
            u32 wimg = wb2[bufi] + kx * W_IMG;
            int kc2 = 2 * kk;
            u32 af[6][4];
            {
                int arow_off = ((g & 1) << 3) + l7;
                int achunk = kc2 + (g >> 1);
                u32 axor = (u32)(achunk * 16) ^ ((u32)l7 << 4);
#pragma unroll
                for (int mi = 0; mi < 6; ++mi) {
                    u32 a = wimg + (mi * 16 + arow_off) * 128 + axor;
                    ldsm4(af[mi][0], af[mi][1], af[mi][2], af[mi][3], a);
                }
            }
            u32 bf[5][2];
            {
                int px0 = wpx + kx + ((g >> 1) << 3) + l7;
                int chunk = kc2 + (g & 1);
                u32 a0 = actbuf + px0 * 128 + (((u32)(chunk * 16)) ^ (((u32)px0 & 7) << 4));
                ldsm4(bf[0][0], bf[0][1], bf[1][0], bf[1][1], a0);
                int px1 = px0 + 16;
                u32 a1 = actbuf + px1 * 128 + (((u32)(chunk * 16)) ^ (((u32)px1 & 7) << 4));
                ldsm4(bf[2][0], bf[2][1], bf[3][0], bf[3][1], a1);
                int px2 = wpx + kx + 32 + l7;
                u32 a2 = actbuf + px2 * 128 + (((u32)(chunk * 16)) ^ (((u32)px2 & 7) << 4));
                ldsm2(bf[4][0], bf[4][1], a2);
            }
#pragma unroll
            for (int mi = 0; mi < 6; ++mi)
#pragma unroll
                for (int nt = 0; nt < 5; ++nt)
                    mma16816(acc[mi][nt], af[mi], bf[nt]);
        };

        if ((r & 1) == 0) {
#pragma unroll
            for (int kx = 0; kx < 3; ++kx) {
                chunk_body(kx, 0); chunk_body(kx, 1);
                chunk_body(kx, 2); chunk_body(kx, 3);
            }
        } else {
#pragma unroll
            for (int kx = 0; kx < 3; ++kx) {
                chunk_body(kx, 0); chunk_body(kx, 1);
            }
        }
        __syncthreads();
    }

    // ---- epilogue: BN + ReLU ----
    int lrow = lane >> 2;
    int lcol = (lane & 3) * 2;

    if (PHASE == 0) {
        __half* s_ep = (__half*)smc;     // [2 slab][320 px][64 slot]
#pragma unroll
        for (int mi = 0; mi < 6; ++mi) {
            int oc0 = mi * 16 + lrow;
            int oc1 = oc0 + 8;
            float a0 = gg[oc0] * rsqrtf(vv[oc0] + 1e-3f);
            float e0 = bb_[oc0] - mm[oc0] * a0;
            float a1 = gg[oc1] * rsqrtf(vv[oc1] + 1e-3f);
            float e1 = bb_[oc1] - mm[oc1] * a1;
            int s0 = (oc0 >> 6) * 20480 + (oc0 & 63);
            int s1 = (oc1 >> 6) * 20480 + (oc1 & 63);
#pragma unroll
            for (int nt = 0; nt < 5; ++nt) {
                int px = wpx + nt * 8 + lcol;
                s_ep[s0 + px * 64]        = __float2half_rn(fmaxf(fmaf(acc[mi][nt][0], a0, e0), 0.f));
                s_ep[s0 + (px + 1) * 64]  = __float2half_rn(fmaxf(fmaf(acc[mi][nt][1], a0, e0), 0.f));
                s_ep[s1 + px * 64]        = __float2half_rn(fmaxf(fmaf(acc[mi][nt][2], a1, e1), 0.f));
                s_ep[s1 + (px + 1) * 64]  = __float2half_rn(fmaxf(fmaf(acc[mi][nt][3], a1, e1), 0.f));
            }
        }
        __syncthreads();
        const uint4* src = (const uint4*)s_ep;
        size_t rowb = ((size_t)b * 322 + y + 1) * NSLAB;
        // slab0: 320x8 uint4; slab1: 320x4 (ch 0..3 only)
        for (int idx = tid; idx < 3840; idx += 256) {
            int slab, p, ch;
            if (idx < 2560) { slab = 0; p = idx >> 3; ch = idx & 7; }
            else { slab = 1; int rem = idx - 2560; p = rem >> 2; ch = rem & 3; }
            uint4 v = src[slab * 2560 + p * 8 + ch];
            *(uint4*)((char*)g_act1 + ((rowb + slab) * 328 + p + 1) * 128 + ch * 16) = v;
        }
    } else {
#pragma unroll
        for (int mi = 0; mi < 6; ++mi) {
            int oc0 = mi * 16 + lrow;
            int oc1 = oc0 + 8;
            float a0 = gg[oc0] * rsqrtf(vv[oc0] + 1e-3f);
            float e0 = bb_[oc0] - mm[oc0] * a0;
            float a1 = gg[oc1] * rsqrtf(vv[oc1] + 1e-3f);
            float e1 = bb_[oc1] - mm[oc1] * a1;
#pragma unroll
            for (int nt = 0; nt < 5; ++nt) {
                int px = wpx + nt * 8 + lcol;
                float v00 = fmaxf(fmaf(acc[mi][nt][0], a0, e0), 0.f);
                float v01 = fmaxf(fmaf(acc[mi][nt][1], a0, e0), 0.f);
                float v10 = fmaxf(fmaf(acc[mi][nt][2], a1, e1), 0.f);
                float v11 = fmaxf(fmaf(acc[mi][nt][3], a1, e1), 0.f);
                *reinterpret_cast<float2*>(
                    &outp[((size_t)(b * CCH + oc0) * BEV + y) * BEV + px]) =
                    make_float2(v00, v01);
                *reinterpret_cast<float2*>(
                    &outp[((size_t)(b * CCH + oc1) * BEV + y) * BEV + px]) =
                    make_float2(v10, v11);
            }
        }
    }
}

// ---------------------------------------------------------------------------
// Launch
// ---------------------------------------------------------------------------
extern "C" void kernel_launch(void* const* d_in, const int* in_sizes, int n_in,
                              void* d_out, int out_size)
{
    const float* feats = (const float*)d_in[0];
    const float* l2i   = (const float*)d_in[1];
    const float* he    = (const float*)d_in[2];
    const float* dw1   = (const float*)d_in[3];
    const float* db1   = (const float*)d_in[4];
    const float* dw2   = (const float*)d_in[5];
    const float* db2   = (const float*)d_in[6];
    const float* sw1   = (const float*)d_in[7];
    const float* sb1   = (const float*)d_in[8];
    const float* sw2   = (const float*)d_in[9];
    const float* sb2   = (const float*)d_in[10];
    const float* c1w   = (const float*)d_in[11];
    const float* b1g   = (const float*)d_in[12];
    const float* b1b   = (const float*)d_in[13];
    const float* b1m   = (const float*)d_in[14];
    const float* b1v   = (const float*)d_in[15];
    const float* c2w   = (const float*)d_in[16];
    const float* b2g   = (const float*)d_in[17];
    const float* b2b   = (const float*)d_in[18];
    const float* b2m   = (const float*)d_in[19];
    const float* b2v   = (const float*)d_in[20];
    float* out = (float*)d_out;

    transpose_kernel<<<dim3(11, 3, NB * FEAT_H), dim3(32, 8)>>>(feats);
    prep_kernel<<<HID + 3, HID>>>(dw2, sw1, db2, he, sb1);
    prep_seg1_kernel<<<1, HID>>>(dw1, db1);
    prep_seg2_kernel<<<65, HID>>>(dw1, db1);
    prep_wpack_kernel<<<36, 256>>>(c1w, c2w);

    size_t lsm = (size_t)(CCH * 32) * 8 + (192 + 64 + 64) * 4 +
                 (size_t)8 * 96 * 16 + 2 * 32 * 64 * 2;
    cudaFuncSetAttribute(lift_kernel, cudaFuncAttributeMaxDynamicSharedMemorySize, (int)lsm);
    lift_kernel<<<444, 256, lsm>>>(l2i, sw1, sw2, sb2);

    size_t csm = 2 * ACT_SZ + 2 * W_SZ;   // 157,696 B
    cudaFuncSetAttribute(mma_conv_kernel<0>, cudaFuncAttributeMaxDynamicSharedMemorySize, (int)csm);
    cudaFuncSetAttribute(mma_conv_kernel<1>, cudaFuncAttributeMaxDynamicSharedMemorySize, (int)csm);

    mma_conv_kernel<0><<<NB * BEV, 256, csm>>>(b1g, b1b, b1m, b1v, out);
    mma_conv_kernel<1><<<NB * BEV, 256, csm>>>(b2g, b2b, b2m, b2v, out);
}